// round 7
// baseline (speedup 1.0000x reference)
#include <cuda_runtime.h>
#include <math.h>

#define MAXB 16384
#define DT 0.01f
#define FULLMASK 0xffffffffu
#define TRI(i,j) ((i)*((i)+1)/2+(j))

__constant__ float c_LOWER[6] = {-6.28f,-6.28f,-3.14f,-6.28f,-6.28f,-6.28f};
__constant__ float c_UPPER[6] = { 6.28f, 6.28f, 3.14f, 6.28f, 6.28f, 6.28f};
__constant__ float c_EFFORT[6]= {150.f,150.f,150.f,28.f,28.f,28.f};

__device__ float g_kqd[4][MAXB*6];
__device__ int   g_viol[4];

// tf32-prepped weights, float4-packed B fragments.
// layer1 (K=16): [n*4+tig] = {W[n][tig],W[n][tig+4],W[n][8+tig],W[n][12+tig]} (col12=bias)
// layer-128 (K=128): [(n*8+ktp)*4+tig] = {W[n][16ktp+tig],W[n][16ktp+tig+4],W[n][16ktp+8+tig],W[n][16ktp+12+tig]}
__device__ float4 g_W1L4 [128*4];
__device__ float4 g_W2L4 [128*8*4];
__device__ float4 g_W3L4 [24*8*4];
__device__ float4 g_W1V4 [128*4];
__device__ float4 g_W2V4 [128*8*4];
__device__ float4 g_W2VT4[128*8*4];
__device__ float4 g_W1VT4[16*8*4];

__device__ __forceinline__ float rna(float x){
  unsigned u; asm("cvt.rna.tf32.f32 %0, %1;":"=r"(u):"f"(x)); return __uint_as_float(u);
}
__device__ __forceinline__ float sp_f(float x){ return fmaxf(x,0.f)+__logf(1.f+__expf(-fabsf(x))); }
__device__ __forceinline__ float sg_f(float x){ return __fdividef(1.f,1.f+__expf(-x)); }
__device__ __forceinline__ void mma8(float&d0,float&d1,float&d2,float&d3,
    unsigned a0,unsigned a1,unsigned a2,unsigned a3,unsigned b0,unsigned b1){
  asm volatile("mma.sync.aligned.m16n8k8.row.col.f32.tf32.tf32.f32 "
    "{%0,%1,%2,%3},{%4,%5,%6,%7},{%8,%9},{%0,%1,%2,%3};"
    :"+f"(d0),"+f"(d1),"+f"(d2),"+f"(d3)
    :"r"(a0),"r"(a1),"r"(a2),"r"(a3),"r"(b0),"r"(b1));
}
__device__ __forceinline__ void ldsm4(unsigned&r0,unsigned&r1,unsigned&r2,unsigned&r3,unsigned a){
  asm volatile("ldmatrix.sync.aligned.m8n8.x4.shared.b16 {%0,%1,%2,%3},[%4];"
    :"=r"(r0),"=r"(r1),"=r"(r2),"=r"(r3):"r"(a));
}
__device__ __forceinline__ int swz16(int r,int c){ return (r<<7)+(c^((r&7)<<2)); }
#define F2U __float_as_uint
#define NBARL() asm volatile("bar.sync 1, 224;" ::: "memory")

__device__ __forceinline__ float calc_qs(int S,const float* obs,int e,int j){
  float q0=obs[e*12+j], qd0=obs[e*12+6+j];
  if (S==0) return q0;
  if (S==1) return q0+0.5f*DT*qd0;
  if (S==2) return q0+0.5f*DT*(qd0+0.5f*DT*g_kqd[0][e*6+j]);
  return q0+DT*(qd0+0.5f*DT*g_kqd[1][e*6+j]);
}
__device__ __forceinline__ float calc_qds(int S,const float* obs,int e,int j){
  float qd0=obs[e*12+6+j];
  if (S==0) return qd0;
  if (S==1) return qd0+0.5f*DT*g_kqd[0][e*6+j];
  if (S==2) return qd0+0.5f*DT*g_kqd[1][e*6+j];
  return qd0+DT*g_kqd[2][e*6+j];
}

__global__ void zero_viol_kernel(){ if (threadIdx.x<4) g_viol[threadIdx.x]=0; }

__global__ void init_kernel(const float* __restrict__ obs,
    const float* __restrict__ W1L,const float* __restrict__ b1L,
    const float* __restrict__ W2L,const float* __restrict__ W3L,
    const float* __restrict__ W1V,const float* __restrict__ b1V,const float* __restrict__ W2V,
    int B){
  int i=blockIdx.x*blockDim.x+threadIdx.x;
  if (i<512){
    int n=i>>2, tig=i&3; int ks[4]={tig,tig+4,8+tig,12+tig}; float v[4];
#pragma unroll
    for(int t=0;t<4;t++){ int k=ks[t]; v[t]=(k<12)?W1L[n*12+k]:((k==12)?b1L[n]:0.f); }
    g_W1L4[i]=make_float4(rna(v[0]),rna(v[1]),rna(v[2]),rna(v[3]));
  } else if (i<4608){ int j=i-512; int n=j>>5, ktp=(j>>2)&7, tig=j&3; int k0=16*ktp+tig;
    g_W2L4[j]=make_float4(rna(W2L[n*128+k0]),rna(W2L[n*128+k0+4]),rna(W2L[n*128+k0+8]),rna(W2L[n*128+k0+12]));
  } else if (i<5376){ int j=i-4608; int n=j>>5, ktp=(j>>2)&7, tig=j&3; int k0=16*ktp+tig;
    float4 o=make_float4(0.f,0.f,0.f,0.f);
    if (n<21) o=make_float4(rna(W3L[n*128+k0]),rna(W3L[n*128+k0+4]),rna(W3L[n*128+k0+8]),rna(W3L[n*128+k0+12]));
    g_W3L4[j]=o;
  } else if (i<5888){ int j=i-5376;
    int n=j>>2, tig=j&3; int ks[4]={tig,tig+4,8+tig,12+tig}; float v[4];
#pragma unroll
    for(int t=0;t<4;t++){ int k=ks[t]; v[t]=(k<12)?W1V[n*12+k]:((k==12)?b1V[n]:0.f); }
    g_W1V4[j]=make_float4(rna(v[0]),rna(v[1]),rna(v[2]),rna(v[3]));
  } else if (i<9984){ int j=i-5888; int n=j>>5, ktp=(j>>2)&7, tig=j&3; int k0=16*ktp+tig;
    g_W2V4[j]=make_float4(rna(W2V[n*128+k0]),rna(W2V[n*128+k0+4]),rna(W2V[n*128+k0+8]),rna(W2V[n*128+k0+12]));
  } else if (i<14080){ int j=i-9984; int n=j>>5, ktp=(j>>2)&7, tig=j&3; int k0=16*ktp+tig;
    g_W2VT4[j]=make_float4(rna(W2V[k0*128+n]),rna(W2V[(k0+4)*128+n]),rna(W2V[(k0+8)*128+n]),rna(W2V[(k0+12)*128+n]));
  } else if (i<14592){ int j=i-14080; int n=j>>5, ktp=(j>>2)&7, tig=j&3; int k0=16*ktp+tig;
    float4 o=make_float4(0.f,0.f,0.f,0.f);
    if (n<12) o=make_float4(rna(W1V[k0*12+n]),rna(W1V[(k0+4)*12+n]),rna(W1V[(k0+8)*12+n]),rna(W1V[(k0+12)*12+n]));
    g_W1VT4[j]=o;
  }
  unsigned b0=0,b1=0;
  if (i<B*6){
    int e=i/6, j=i-e*6;
    float q0=obs[e*12+j], qd0=obs[e*12+6+j];
    float lo=c_LOWER[j]+0.1f, up=c_UPPER[j]-0.1f;
    float qs1=q0+0.5f*DT*qd0;
    if (q0 <=lo || q0 >=up) b0=1u<<j;
    if (qs1<=lo || qs1>=up) b1=1u<<j;
  }
  unsigned r0=__reduce_or_sync(FULLMASK,b0);
  unsigned r1=__reduce_or_sync(FULLMASK,b1);
  if ((threadIdx.x&31)==0){
    if (r0) atomicOr(&g_viol[0],(int)r0);
    if (r1) atomicOr(&g_viol[1],(int)r1);
  }
}

// smem layout (floats)
#define S_A0   0        // 112 x 20  A-matrices (layer1 input), per-warp tiles
#define S_VIN  2240     // 16 x 20   V-net input
#define S_H    2560     // 7 tiles x (16x128)  L hidden (warp-private, in-place L1->L2->L3)
#define S_H1V  16896    // 16x128 V hidden / r1
#define S_R2   18944    // 16x128 r2
#define S_SGA  20992    // 16x132 published sigmoid (layers 1,3)
#define S_SGB  23104    // 16x132 published sigmoid (layer 2)
#define S_SL   25216    // 16 el x 176 (ch*25+c) L outputs
#define S_SG   28032    // 16x12 gravity partials
#define SMEM_FLOATS 28224

__global__ void __launch_bounds__(256,2)
accel_mma_kernel(int S, const float* __restrict__ obs, const float* __restrict__ action,
    const float* __restrict__ b2L, const float* __restrict__ b3L,
    const float* __restrict__ b2V, const float* __restrict__ W3V, int B)
{
  extern __shared__ float sm[];
  const int tid=threadIdx.x, w=tid>>5, lane=tid&31;
  const int gid=lane>>2, tig=lane&3;
  const int eb=blockIdx.x*16;
  const int vm=g_viol[S];
  const unsigned smb=(unsigned)__cvta_generic_to_shared(sm);

  const int sub=lane>>3, l7=lane&7;
  const int lm_row = l7 + ((sub&1)<<3);
  const unsigned lm_koff = (unsigned)(l7>>1);
  const unsigned lm_cfix4 = (unsigned)(((sub&2)<<3) ^ ((l7&1)<<4));
  const unsigned base_A0w = smb + S_A0*4  + w*1280 + lm_row*80 + ((sub&2)<<3);
  const unsigned base_VIN = smb + S_VIN*4 + lm_row*80 + ((sub&2)<<3);
  const unsigned base_Hw  = smb + (S_H + w*2048)*4 + lm_row*512 + lm_cfix4;
  const unsigned base_H1V = smb + S_H1V*4 + lm_row*512 + lm_cfix4;
  const unsigned base_R2  = smb + S_R2*4  + lm_row*512 + lm_cfix4;

  // ---------- P0: build A matrices (warp-private) ----------
  {
    int el=lane&15, half=lane>>4;
    int e=eb+el; if (e>=B) e=B-1;
    float t16[16];
#pragma unroll
    for(int k=0;k<16;k++) t16[k]=0.f;
    if (w==0 || w==7){
#pragma unroll
      for(int j=0;j<6;j++){ float qj=calc_qs(S,obs,e,j); t16[2*j]=cosf(qj); t16[2*j+1]=sinf(qj); }
      t16[12]=1.f;
    } else {
      int p=w-1; float qp=calc_qs(S,obs,e,p);
      t16[2*p]=-sinf(qp); t16[2*p+1]=cosf(qp);
    }
    int rbase = (w<7)? (S_A0 + (w*16+el)*20) : (S_VIN + el*20);
#pragma unroll
    for(int k=0;k<8;k++) sm[rbase+half*8+k]=rna(t16[half*8+k]);
  }
  __syncwarp();

  if (w<7){
    // ================= L-chain: warp w owns channel w (M-tile w) ================
    // ---- L1 (K=16) ----
    float D1[16][4]={};
    {
      unsigned a0[4],a1[4];
      ldsm4(a0[0],a0[1],a0[2],a0[3], base_A0w);
      ldsm4(a1[0],a1[1],a1[2],a1[3], base_A0w+32);
#pragma unroll
      for(int nt=0;nt<16;nt++){
        float4 bf=__ldg(&g_W1L4[(nt*8+gid)*4+tig]);
        mma8(D1[nt][0],D1[nt][1],D1[nt][2],D1[nt][3],a0[0],a0[1],a0[2],a0[3],F2U(bf.x),F2U(bf.y));
        mma8(D1[nt][0],D1[nt][1],D1[nt][2],D1[nt][3],a1[0],a1[1],a1[2],a1[3],F2U(bf.z),F2U(bf.w));
      }
    }
    if (w==0){
#pragma unroll
      for(int nt=0;nt<16;nt++){
        int c0=nt*8+tig*2;
        *(float2*)&sm[S_SGA+gid*132+c0]    =make_float2(sg_f(D1[nt][0]),sg_f(D1[nt][1]));
        *(float2*)&sm[S_SGA+(gid+8)*132+c0]=make_float2(sg_f(D1[nt][2]),sg_f(D1[nt][3]));
      }
    }
    NBARL();
#pragma unroll
    for(int nt=0;nt<16;nt++){
      int c0=nt*8+tig*2;
      float o0,o1,o2,o3;
      if (w==0){ o0=sp_f(D1[nt][0]);o1=sp_f(D1[nt][1]);o2=sp_f(D1[nt][2]);o3=sp_f(D1[nt][3]); }
      else {
        float2 sA=*(float2*)&sm[S_SGA+gid*132+c0];
        float2 sB=*(float2*)&sm[S_SGA+(gid+8)*132+c0];
        o0=sA.x*D1[nt][0]; o1=sA.y*D1[nt][1]; o2=sB.x*D1[nt][2]; o3=sB.y*D1[nt][3];
      }
      *(float2*)&sm[S_H+w*2048+swz16(gid,c0)]  =make_float2(rna(o0),rna(o1));
      *(float2*)&sm[S_H+w*2048+swz16(gid+8,c0)]=make_float2(rna(o2),rna(o3));
    }
    __syncwarp();
    // ---- L2 (K=128, warp-private A) ----
    float D2[16][4]={};
#pragma unroll 2
    for(int ktp=0;ktp<8;ktp++){
      unsigned a0[4],a1[4];
      ldsm4(a0[0],a0[1],a0[2],a0[3], base_Hw + (((unsigned)(2*ktp)  ^lm_koff)<<5));
      ldsm4(a1[0],a1[1],a1[2],a1[3], base_Hw + (((unsigned)(2*ktp+1)^lm_koff)<<5));
#pragma unroll
      for(int nt=0;nt<16;nt++){
        float4 bf=__ldg(&g_W2L4[((nt*8+gid)*8+ktp)*4+tig]);
        mma8(D2[nt][0],D2[nt][1],D2[nt][2],D2[nt][3],a0[0],a0[1],a0[2],a0[3],F2U(bf.x),F2U(bf.y));
        mma8(D2[nt][0],D2[nt][1],D2[nt][2],D2[nt][3],a1[0],a1[1],a1[2],a1[3],F2U(bf.z),F2U(bf.w));
      }
    }
    if (w==0){
#pragma unroll
      for(int nt=0;nt<16;nt++){
        int c0=nt*8+tig*2;
        float bv0=__ldg(b2L+c0), bv1=__ldg(b2L+c0+1);
        *(float2*)&sm[S_SGB+gid*132+c0]    =make_float2(sg_f(D2[nt][0]+bv0),sg_f(D2[nt][1]+bv1));
        *(float2*)&sm[S_SGB+(gid+8)*132+c0]=make_float2(sg_f(D2[nt][2]+bv0),sg_f(D2[nt][3]+bv1));
      }
    }
    NBARL();
#pragma unroll
    for(int nt=0;nt<16;nt++){
      int c0=nt*8+tig*2;
      float o0,o1,o2,o3;
      if (w==0){
        float bv0=__ldg(b2L+c0), bv1=__ldg(b2L+c0+1);
        o0=sp_f(D2[nt][0]+bv0);o1=sp_f(D2[nt][1]+bv1);o2=sp_f(D2[nt][2]+bv0);o3=sp_f(D2[nt][3]+bv1);
      } else {
        float2 sA=*(float2*)&sm[S_SGB+gid*132+c0];
        float2 sB=*(float2*)&sm[S_SGB+(gid+8)*132+c0];
        o0=sA.x*D2[nt][0]; o1=sA.y*D2[nt][1]; o2=sB.x*D2[nt][2]; o3=sB.y*D2[nt][3];
      }
      *(float2*)&sm[S_H+w*2048+swz16(gid,c0)]  =make_float2(rna(o0),rna(o1));
      *(float2*)&sm[S_H+w*2048+swz16(gid+8,c0)]=make_float2(rna(o2),rna(o3));
    }
    __syncwarp();
    // ---- L3 (N=24) ----
    float D3[3][4]={};
#pragma unroll 2
    for(int ktp=0;ktp<8;ktp++){
      unsigned a0[4],a1[4];
      ldsm4(a0[0],a0[1],a0[2],a0[3], base_Hw + (((unsigned)(2*ktp)  ^lm_koff)<<5));
      ldsm4(a1[0],a1[1],a1[2],a1[3], base_Hw + (((unsigned)(2*ktp+1)^lm_koff)<<5));
#pragma unroll
      for(int nt=0;nt<3;nt++){
        float4 bf=__ldg(&g_W3L4[((nt*8+gid)*8+ktp)*4+tig]);
        mma8(D3[nt][0],D3[nt][1],D3[nt][2],D3[nt][3],a0[0],a0[1],a0[2],a0[3],F2U(bf.x),F2U(bf.y));
        mma8(D3[nt][0],D3[nt][1],D3[nt][2],D3[nt][3],a1[0],a1[1],a1[2],a1[3],F2U(bf.z),F2U(bf.w));
      }
    }
    if (w==0){
#pragma unroll
      for(int nt=0;nt<3;nt++){
        int c0=nt*8+tig*2;
        float bb0=(c0<21)?__ldg(b3L+c0):0.f, bb1=(c0+1<21)?__ldg(b3L+c0+1):0.f;
        *(float2*)&sm[S_SGA+gid*132+c0]    =make_float2(sg_f(D3[nt][0]+bb0),sg_f(D3[nt][1]+bb1));
        *(float2*)&sm[S_SGA+(gid+8)*132+c0]=make_float2(sg_f(D3[nt][2]+bb0),sg_f(D3[nt][3]+bb1));
      }
    }
    NBARL();
#pragma unroll
    for(int nt=0;nt<3;nt++){
      int c0=nt*8+tig*2;
      float o0,o1,o2,o3;
      if (w==0){
        float bb0=(c0<21)?__ldg(b3L+c0):0.f, bb1=(c0+1<21)?__ldg(b3L+c0+1):0.f;
        o0=sp_f(D3[nt][0]+bb0);o1=sp_f(D3[nt][1]+bb1);o2=sp_f(D3[nt][2]+bb0);o3=sp_f(D3[nt][3]+bb1);
      } else {
        float2 sA=*(float2*)&sm[S_SGA+gid*132+c0];
        float2 sB=*(float2*)&sm[S_SGA+(gid+8)*132+c0];
        o0=sA.x*D3[nt][0]; o1=sA.y*D3[nt][1]; o2=sB.x*D3[nt][2]; o3=sB.y*D3[nt][3];
      }
      sm[S_SL+gid*176+w*25+c0]=o0;      sm[S_SL+gid*176+w*25+c0+1]=o1;
      sm[S_SL+(gid+8)*176+w*25+c0]=o2;  sm[S_SL+(gid+8)*176+w*25+c0+1]=o3;
    }
  } else {
    // ================= V-chain (warp 7, warp-private) ================
    // ---- V1 (K=16) ----
    float DV[16][4]={};
    {
      unsigned a0[4],a1[4];
      ldsm4(a0[0],a0[1],a0[2],a0[3], base_VIN);
      ldsm4(a1[0],a1[1],a1[2],a1[3], base_VIN+32);
#pragma unroll
      for(int nt=0;nt<16;nt++){
        float4 bf=__ldg(&g_W1V4[(nt*8+gid)*4+tig]);
        mma8(DV[nt][0],DV[nt][1],DV[nt][2],DV[nt][3],a0[0],a0[1],a0[2],a0[3],F2U(bf.x),F2U(bf.y));
        mma8(DV[nt][0],DV[nt][1],DV[nt][2],DV[nt][3],a1[0],a1[1],a1[2],a1[3],F2U(bf.z),F2U(bf.w));
      }
    }
#pragma unroll
    for(int nt=0;nt<16;nt++){
      int c0=nt*8+tig*2;
      *(float2*)&sm[S_H1V+swz16(gid,c0)]  =make_float2(rna(sp_f(DV[nt][0])),rna(sp_f(DV[nt][1])));
      *(float2*)&sm[S_H1V+swz16(gid+8,c0)]=make_float2(rna(sp_f(DV[nt][2])),rna(sp_f(DV[nt][3])));
    }
    __syncwarp();
    // ---- V2 ----
    float DW[16][4]={};
#pragma unroll 2
    for(int ktp=0;ktp<8;ktp++){
      unsigned a0[4],a1[4];
      ldsm4(a0[0],a0[1],a0[2],a0[3], base_H1V + (((unsigned)(2*ktp)  ^lm_koff)<<5));
      ldsm4(a1[0],a1[1],a1[2],a1[3], base_H1V + (((unsigned)(2*ktp+1)^lm_koff)<<5));
#pragma unroll
      for(int nt=0;nt<16;nt++){
        float4 bf=__ldg(&g_W2V4[((nt*8+gid)*8+ktp)*4+tig]);
        mma8(DW[nt][0],DW[nt][1],DW[nt][2],DW[nt][3],a0[0],a0[1],a0[2],a0[3],F2U(bf.x),F2U(bf.y));
        mma8(DW[nt][0],DW[nt][1],DW[nt][2],DW[nt][3],a1[0],a1[1],a1[2],a1[3],F2U(bf.z),F2U(bf.w));
      }
    }
#pragma unroll
    for(int nt=0;nt<16;nt++){
      int c0=nt*8+tig*2;
      float bv0=__ldg(b2V+c0),bv1=__ldg(b2V+c0+1),w30=__ldg(W3V+c0),w31=__ldg(W3V+c0+1);
      *(float2*)&sm[S_R2+swz16(gid,c0)]  =make_float2(rna(w30*sg_f(DW[nt][0]+bv0)),rna(w31*sg_f(DW[nt][1]+bv1)));
      *(float2*)&sm[S_R2+swz16(gid+8,c0)]=make_float2(rna(w30*sg_f(DW[nt][2]+bv0)),rna(w31*sg_f(DW[nt][3]+bv1)));
    }
    __syncwarp();
    // ---- V backward: r1 = (W2V^T r2) .* s1v ----
    float DB[16][4]={};
#pragma unroll 2
    for(int ktp=0;ktp<8;ktp++){
      unsigned a0[4],a1[4];
      ldsm4(a0[0],a0[1],a0[2],a0[3], base_R2 + (((unsigned)(2*ktp)  ^lm_koff)<<5));
      ldsm4(a1[0],a1[1],a1[2],a1[3], base_R2 + (((unsigned)(2*ktp+1)^lm_koff)<<5));
#pragma unroll
      for(int nt=0;nt<16;nt++){
        float4 bf=__ldg(&g_W2VT4[((nt*8+gid)*8+ktp)*4+tig]);
        mma8(DB[nt][0],DB[nt][1],DB[nt][2],DB[nt][3],a0[0],a0[1],a0[2],a0[3],F2U(bf.x),F2U(bf.y));
        mma8(DB[nt][0],DB[nt][1],DB[nt][2],DB[nt][3],a1[0],a1[1],a1[2],a1[3],F2U(bf.z),F2U(bf.w));
      }
    }
#pragma unroll
    for(int nt=0;nt<16;nt++){
      int c0=nt*8+tig*2;
      float2 hA=*(float2*)&sm[S_H1V+swz16(gid,c0)];
      float2 hB=*(float2*)&sm[S_H1V+swz16(gid+8,c0)];
      float r0=DB[nt][0]*(1.f-__expf(-hA.x)), r1=DB[nt][1]*(1.f-__expf(-hA.y));
      float r2=DB[nt][2]*(1.f-__expf(-hB.x)), r3=DB[nt][3]*(1.f-__expf(-hB.y));
      *(float2*)&sm[S_H1V+swz16(gid,c0)]  =make_float2(rna(r0),rna(r1));
      *(float2*)&sm[S_H1V+swz16(gid+8,c0)]=make_float2(rna(r2),rna(r3));
    }
    __syncwarp();
    // ---- grad = r1 @ W1V ----
    float DG[2][4]={};
#pragma unroll 2
    for(int ktp=0;ktp<8;ktp++){
      unsigned a0[4],a1[4];
      ldsm4(a0[0],a0[1],a0[2],a0[3], base_H1V + (((unsigned)(2*ktp)  ^lm_koff)<<5));
      ldsm4(a1[0],a1[1],a1[2],a1[3], base_H1V + (((unsigned)(2*ktp+1)^lm_koff)<<5));
#pragma unroll
      for(int nt=0;nt<2;nt++){
        float4 bf=__ldg(&g_W1VT4[((nt*8+gid)*8+ktp)*4+tig]);
        mma8(DG[nt][0],DG[nt][1],DG[nt][2],DG[nt][3],a0[0],a0[1],a0[2],a0[3],F2U(bf.x),F2U(bf.y));
        mma8(DG[nt][0],DG[nt][1],DG[nt][2],DG[nt][3],a1[0],a1[1],a1[2],a1[3],F2U(bf.z),F2U(bf.w));
      }
    }
#pragma unroll
    for(int nt=0;nt<2;nt++){
      int c=nt*8+tig*2;
      if (c<12){ sm[S_SG+gid*12+c]=DG[nt][0]; sm[S_SG+(gid+8)*12+c]=DG[nt][2]; }
      if (c+1<12){ sm[S_SG+gid*12+c+1]=DG[nt][1]; sm[S_SG+(gid+8)*12+c+1]=DG[nt][3]; }
    }
  }
  __syncthreads();

  // ---------- P5: assembly + Cholesky solve (warps 0-3, 8 lanes/element) ----------
  if (w<4){
    int gl=lane&7, grp=lane>>3, eloc=w*4+grp;
    int e=eb+eloc; bool valid=(e<B); if(!valid) e=B-1;
    const float* SLe=sm+S_SL+eloc*176;
    float* SDel=sm+S_A0+eloc*24;
    float qd6[6];
#pragma unroll
    for(int j=0;j<6;j++) qd6[j]=calc_qds(S,obs,e,j);
    if (gl<7){
#pragma unroll
      for(int t=0;t<3;t++){
        int m=gl*3+t;
        if (m<21){
          float s=0.f;
#pragma unroll
          for(int p=0;p<6;p++) s+=qd6[p]*SLe[(1+p)*25+m];
          SDel[m]=s;
        }
      }
    }
    __syncwarp();
    int li=(gl<6)?gl:5;
    float w6[6],u6[6],Dq[6];
#pragma unroll
    for(int k=0;k<6;k++){
      float sw=0.f,su=0.f,sd=0.f;
#pragma unroll
      for(int i2=0;i2<6;i2++) if (i2>=k){
        int m=TRI(i2,k); float a=qd6[i2];
        sw+=SLe[m]*a; su+=SLe[(1+li)*25+m]*a; sd+=SDel[m]*a;
      }
      w6[k]=sw; u6[k]=su; Dq[k]=sd;
    }
    float term2=0.f;
#pragma unroll
    for(int k=0;k<6;k++) term2+=w6[k]*u6[k];
    int base=li*(li+1)/2;
    float Dw=0.f,LDq=0.f;
#pragma unroll
    for(int j2=0;j2<6;j2++) if (j2<=li){ Dw+=SDel[base+j2]*w6[j2]; LDq+=SLe[base+j2]*Dq[j2]; }
    float ci=Dw+LDq-term2;
    float qsi=calc_qs(S,obs,e,li);
    float gi=-sm[S_SG+eloc*12+2*li]*sinf(qsi)+sm[S_SG+eloc*12+2*li+1]*cosf(qsi);
    float lo=c_LOWER[li]+0.1f, up=c_UPPER[li]-0.1f;
    float fi;
    if ((vm>>li)&1) fi=(qsi<=lo)?c_EFFORT[li]:((qsi>=up)?-c_EFFORT[li]:0.f);
    else            fi=-5.f*(1.f/(qsi-lo)-1.f/(up-qsi));
    float tau=__ldg(action+e*6+li)*c_EFFORT[li];
    float rhs=tau-ci-gi-fi;
    int gb=lane&~7;
    float accf=rhs, yvv=0.f;
#pragma unroll
    for(int j2=0;j2<6;j2++){
      float yj=__shfl_sync(FULLMASK,accf,gb+j2)/SLe[TRI(j2,j2)];
      if (gl==j2) yvv=yj;
      if (gl>j2 && gl<6) accf-=SLe[base+j2]*yj;
    }
    float acc2=yvv, xi=0.f;
#pragma unroll
    for(int j2=5;j2>=0;j2--){
      float xj=__shfl_sync(FULLMASK,acc2,gb+j2)/SLe[TRI(j2,j2)];
      if (gl==j2) xi=xj;
      if (gl<j2) acc2-=SLe[TRI(j2,gl)]*xj;
    }
    if (gl<6 && valid) g_kqd[S][e*6+gl]=xi;

    if (S<2){
      unsigned bits=0;
      if (gl<6 && valid){
        float q0=obs[e*12+gl], qd0=obs[e*12+6+gl];
        float qsn=(S==0)? q0+0.5f*DT*(qd0+0.5f*DT*xi) : q0+DT*(qd0+0.5f*DT*xi);
        float lo2=c_LOWER[gl]+0.1f, up2=c_UPPER[gl]-0.1f;
        if (qsn<=lo2 || qsn>=up2) bits=1u<<gl;
      }
      unsigned r=__reduce_or_sync(FULLMASK,bits);
      if (lane==0 && r) atomicOr(&g_viol[S+2],(int)r);
    }
  }
}

__global__ void final_kernel(const float* __restrict__ obs, float* __restrict__ out, int B){
  int idx=blockIdx.x*blockDim.x+threadIdx.x;
  if (idx>=B*6) return;
  int i=idx/6, j=idx-i*6;
  float q0=obs[i*12+j], qd0=obs[i*12+6+j];
  float k0=g_kqd[0][idx],k1=g_kqd[1][idx],k2=g_kqd[2][idx],k3=g_kqd[3][idx];
  float qds1=qd0+0.5f*DT*k0;
  float qds2=qd0+0.5f*DT*k1;
  float qds3=qd0+DT*k2;
  const float c1=DT/6.f;
  float qn=q0+c1*(qd0+2.f*qds1+2.f*qds2+qds3);
  qn=fminf(fmaxf(qn,c_LOWER[j]),c_UPPER[j]);
  float qdn=qd0+c1*(k0+2.f*k1+2.f*k2+k3);
  out[i*12+j]=qn;
  out[i*12+6+j]=qdn;
}

extern "C" void kernel_launch(void* const* d_in, const int* in_sizes, int n_in,
                              void* d_out, int out_size)
{
  const float* obs   =(const float*)d_in[0];
  const float* action=(const float*)d_in[1];
  const float* W1L=(const float*)d_in[2];  const float* b1L=(const float*)d_in[3];
  const float* W2L=(const float*)d_in[4];  const float* b2L=(const float*)d_in[5];
  const float* W3L=(const float*)d_in[6];  const float* b3L=(const float*)d_in[7];
  const float* W1V=(const float*)d_in[8];  const float* b1V=(const float*)d_in[9];
  const float* W2V=(const float*)d_in[10]; const float* b2V=(const float*)d_in[11];
  const float* W3V=(const float*)d_in[12]; const float* b3V=(const float*)d_in[13];
  (void)b3V;
  float* out=(float*)d_out;
  int B=in_sizes[0]/12;
  if (B>MAXB) B=MAXB;

  cudaFuncSetAttribute(accel_mma_kernel, cudaFuncAttributeMaxDynamicSharedMemorySize, SMEM_FLOATS*4);

  int nbE=(B*6+127)/128;
  int nbA=(B+15)/16;
  int nbI=(B*6+255)/256; if (nbI<57) nbI=57;

  zero_viol_kernel<<<1,32>>>();
  init_kernel<<<nbI,256>>>(obs,W1L,b1L,W2L,W3L,W1V,b1V,W2V,B);
  for (int s=0;s<4;s++){
    accel_mma_kernel<<<nbA,256,SMEM_FLOATS*4>>>(s,obs,action,b2L,b3L,b2V,W3V,B);
  }
  final_kernel<<<nbE,128>>>(obs,out,B);
}

// round 11
// speedup vs baseline: 1.1422x; 1.1422x over previous
#include <cuda_runtime.h>
#include <math.h>

#define MAXB 16384
#define DT 0.01f
#define FULLMASK 0xffffffffu
#define TRI(i,j) ((i)*((i)+1)/2+(j))

__constant__ float c_LOWER[6] = {-6.28f,-6.28f,-3.14f,-6.28f,-6.28f,-6.28f};
__constant__ float c_UPPER[6] = { 6.28f, 6.28f, 3.14f, 6.28f, 6.28f, 6.28f};
__constant__ float c_EFFORT[6]= {150.f,150.f,150.f,28.f,28.f,28.f};

__device__ float g_qs [4][MAXB*6];
__device__ float g_qds[4][MAXB*6];
__device__ float g_kqd[3][MAXB*6];
__device__ int   g_viol[4];

// tf32-prepped weights, pair-packed for B fragments
__device__ float2 g_W1L16 [128*2*4];
__device__ float2 g_W2Lp  [128*16*4];
__device__ float2 g_W3L24 [24*16*4];
__device__ float2 g_W1V16 [128*2*4];
__device__ float2 g_W2Vp  [128*16*4];
__device__ float2 g_W2VT  [128*16*4];
__device__ float2 g_W1VT16[16*16*4];

__device__ __forceinline__ float rna(float x){
  unsigned u; asm("cvt.rna.tf32.f32 %0, %1;":"=r"(u):"f"(x)); return __uint_as_float(u);
}
__device__ __forceinline__ float sp_f(float x){ return fmaxf(x,0.f)+__logf(1.f+__expf(-fabsf(x))); }
__device__ __forceinline__ float sg_f(float x){ return __fdividef(1.f,1.f+__expf(-x)); }
__device__ __forceinline__ void mma8(float&d0,float&d1,float&d2,float&d3,
    unsigned a0,unsigned a1,unsigned a2,unsigned a3,unsigned b0,unsigned b1){
  asm volatile("mma.sync.aligned.m16n8k8.row.col.f32.tf32.tf32.f32 "
    "{%0,%1,%2,%3},{%4,%5,%6,%7},{%8,%9},{%0,%1,%2,%3};"
    :"+f"(d0),"+f"(d1),"+f"(d2),"+f"(d3)
    :"r"(a0),"r"(a1),"r"(a2),"r"(a3),"r"(b0),"r"(b1));
}
__device__ __forceinline__ void ldsm4(unsigned&r0,unsigned&r1,unsigned&r2,unsigned&r3,unsigned a){
  asm volatile("ldmatrix.sync.aligned.m8n8.x4.shared.b16 {%0,%1,%2,%3},[%4];"
    :"=r"(r0),"=r"(r1),"=r"(r2),"=r"(r3):"r"(a));
}
__device__ __forceinline__ int swz(int r,int c){ return (r<<7)+(c^((r&7)<<2)); }
#define F2U __float_as_uint

__global__ void zero_viol_kernel(){ if (threadIdx.x<4) g_viol[threadIdx.x]=0; }

// weights prep + stage-0 kinematics + viol[0]
__global__ void init_kernel(const float* __restrict__ obs,
    const float* __restrict__ W1L,const float* __restrict__ b1L,
    const float* __restrict__ W2L,const float* __restrict__ W3L,
    const float* __restrict__ W1V,const float* __restrict__ b1V,const float* __restrict__ W2V,
    int B){
  int i=blockIdx.x*blockDim.x+threadIdx.x;
  if (i<1024){
    int n=i>>3, kt=(i>>2)&1, tig=i&3; int k0=kt*8+tig, k1=k0+4;
    float v0=k0<12?W1L[n*12+k0]:(k0==12?b1L[n]:0.f);
    float v1=k1<12?W1L[n*12+k1]:(k1==12?b1L[n]:0.f);
    g_W1L16[i]=make_float2(rna(v0),rna(v1));
  } else if (i<9216){ int j=i-1024; int n=j>>6,kt=(j>>2)&15,tig=j&3; int k0=kt*8+tig;
    g_W2Lp[j]=make_float2(rna(W2L[n*128+k0]),rna(W2L[n*128+k0+4]));
  } else if (i<10752){ int j=i-9216; int n=j>>6,kt=(j>>2)&15,tig=j&3; int k0=kt*8+tig;
    g_W3L24[j]=make_float2(rna(n<21?W3L[n*128+k0]:0.f),rna(n<21?W3L[n*128+k0+4]:0.f));
  } else if (i<11776){ int j=i-10752; int n=j>>3,kt=(j>>2)&1,tig=j&3; int k0=kt*8+tig,k1=k0+4;
    float v0=k0<12?W1V[n*12+k0]:(k0==12?b1V[n]:0.f);
    float v1=k1<12?W1V[n*12+k1]:(k1==12?b1V[n]:0.f);
    g_W1V16[j]=make_float2(rna(v0),rna(v1));
  } else if (i<19968){ int j=i-11776; int n=j>>6,kt=(j>>2)&15,tig=j&3; int k0=kt*8+tig;
    g_W2Vp[j]=make_float2(rna(W2V[n*128+k0]),rna(W2V[n*128+k0+4]));
  } else if (i<28160){ int j=i-19968; int n=j>>6,kt=(j>>2)&15,tig=j&3; int k0=kt*8+tig;
    g_W2VT[j]=make_float2(rna(W2V[k0*128+n]),rna(W2V[(k0+4)*128+n]));
  } else if (i<29184){ int j=i-28160; int n=j>>6,kt=(j>>2)&15,tig=j&3; int k0=kt*8+tig;
    g_W1VT16[j]=make_float2(rna(n<12?W1V[k0*12+n]:0.f),rna(n<12?W1V[(k0+4)*12+n]:0.f));
  }
  unsigned b0=0;
  if (i<B*6){
    int e=i/6, j=i-e*6;
    float q0=obs[e*12+j], qd0=obs[e*12+6+j];
    g_qs[0][i]=q0; g_qds[0][i]=qd0;
    float lo=c_LOWER[j]+0.1f, up=c_UPPER[j]-0.1f;
    if (q0<=lo || q0>=up) b0=1u<<j;
  }
  unsigned r0=__reduce_or_sync(FULLMASK,b0);
  if ((threadIdx.x&31)==0 && r0) atomicOr(&g_viol[0],(int)r0);
}

// smem layout (floats)
#define S_H    0
#define S_H0   16384
#define S_VIN  18944
#define S_H1V  19264
#define S_R2   21312
#define S_SL   23360
#define S_SG   26560
#define SMEM_FLOATS 26752

__global__ void __launch_bounds__(256,2)
accel_mma_kernel(int S, const float* __restrict__ obs, const float* __restrict__ action,
    float* __restrict__ out,
    const float* __restrict__ b2L, const float* __restrict__ b3L,
    const float* __restrict__ b2V, const float* __restrict__ W3V, int B)
{
  extern __shared__ float sm[];
  const int tid=threadIdx.x, w=tid>>5, lane=tid&31;
  const int gid=lane>>2, tig=lane&3;
  const int eb=blockIdx.x*16;
  const int vm=g_viol[S];
  const unsigned smb=(unsigned)__cvta_generic_to_shared(sm);

  // per-lane ldmatrix address components
  const int sub=lane>>3, l7=lane&7;
  const int lm_row = l7 + ((sub&1)<<3);
  const unsigned lm_koff = (unsigned)(l7>>1);
  const unsigned lm_cfix4 = (unsigned)(((sub&2)<<3) ^ ((l7&1)<<4));
  const unsigned base_H   = smb + S_H*4   + lm_row*512 + lm_cfix4;
  const unsigned base_H1V = smb + S_H1V*4 + lm_row*512 + lm_cfix4;
  const unsigned base_R2  = smb + S_R2*4  + lm_row*512 + lm_cfix4;
  const unsigned base_H0  = smb + S_H0*4  + lm_row*80 + ((sub&2)<<3);
  const unsigned base_VIN = smb + S_VIN*4 + lm_row*80 + ((sub&2)<<3);

  // ---------- P0: build A matrices ----------
  if (tid<128){
    int row=tid, ch=row&7, el=row>>3;
    int e=eb+el; if (e>=B) e=B-1;
    float t16[16];
#pragma unroll
    for(int k=0;k<16;k++) t16[k]=0.f;
    if (ch==0){
#pragma unroll
      for(int j=0;j<6;j++){ float qj=g_qs[S][e*6+j]; t16[2*j]=cosf(qj); t16[2*j+1]=sinf(qj); }
      t16[12]=1.f;
    } else if (ch<7){
      int p=ch-1; float qp=g_qs[S][e*6+p];
      t16[2*p]=-sinf(qp); t16[2*p+1]=cosf(qp);
    }
#pragma unroll
    for(int k=0;k<16;k++) sm[S_H0+row*20+k]=rna(t16[k]);
    if (ch==0){
#pragma unroll
      for(int k=0;k<16;k++) sm[S_VIN+el*20+k]=rna(t16[k]);
    }
  }
  __syncthreads();

  // ---------- P1: V layer1 + L layer1 (K=16) ----------
  {
    float DV[2][4]={};
#pragma unroll
    for(int kt=0;kt<2;kt++){
      unsigned a0,a1,a2,a3; ldsm4(a0,a1,a2,a3, base_VIN + kt*32);
#pragma unroll
      for(int nt=0;nt<2;nt++){
        int n=w*16+nt*8+gid;
        float2 bf=g_W1V16[(n*2+kt)*4+tig];
        mma8(DV[nt][0],DV[nt][1],DV[nt][2],DV[nt][3],a0,a1,a2,a3,F2U(bf.x),F2U(bf.y));
      }
    }
#pragma unroll
    for(int nt=0;nt<2;nt++){
      int c0=w*16+nt*8+tig*2;
      *(float2*)&sm[S_H1V+swz(gid,c0)]  =make_float2(rna(sp_f(DV[nt][0])),rna(sp_f(DV[nt][1])));
      *(float2*)&sm[S_H1V+swz(gid+8,c0)]=make_float2(rna(sp_f(DV[nt][2])),rna(sp_f(DV[nt][3])));
    }
    float D[8][2][4]={};
#pragma unroll
    for(int kt=0;kt<2;kt++){
      float2 bf[2];
#pragma unroll
      for(int nt=0;nt<2;nt++){ int n=w*16+nt*8+gid; bf[nt]=g_W1L16[(n*2+kt)*4+tig]; }
#pragma unroll
      for(int m=0;m<8;m++){
        unsigned a0,a1,a2,a3; ldsm4(a0,a1,a2,a3, base_H0 + m*1280 + kt*32);
#pragma unroll
        for(int nt=0;nt<2;nt++)
          mma8(D[m][nt][0],D[m][nt][1],D[m][nt][2],D[m][nt][3],a0,a1,a2,a3,F2U(bf[nt].x),F2U(bf[nt].y));
      }
    }
#pragma unroll
    for(int m=0;m<8;m++)
#pragma unroll
      for(int nt=0;nt<2;nt++){
        float d0=D[m][nt][0],d1=D[m][nt][1],d2=D[m][nt][2],d3=D[m][nt][3];
        float z0=__shfl_sync(FULLMASK,d0,tig), z1=__shfl_sync(FULLMASK,d1,tig);
        float z2=__shfl_sync(FULLMASK,d2,tig), z3=__shfl_sync(FULLMASK,d3,tig);
        int c0=w*16+nt*8+tig*2;
        float o0,o1,o2,o3;
        if (gid==0){ o0=sp_f(z0);o1=sp_f(z1);o2=sp_f(z2);o3=sp_f(z3); }
        else if (gid<7){ o0=sg_f(z0)*d0;o1=sg_f(z1)*d1;o2=sg_f(z2)*d2;o3=sg_f(z3)*d3; }
        else { o0=0.f;o1=0.f;o2=0.f;o3=0.f; }
        *(float2*)&sm[S_H+swz(m*16+gid,c0)]  =make_float2(rna(o0),rna(o1));
        *(float2*)&sm[S_H+swz(m*16+8+gid,c0)]=make_float2(rna(o2),rna(o3));
      }
  }
  __syncthreads();

  // ---------- P2: V layer2 + L layer2 (in place) ----------
  {
    float DV[2][4]={};
#pragma unroll 4
    for(int kt=0;kt<16;kt++){
      unsigned a0,a1,a2,a3; ldsm4(a0,a1,a2,a3, base_H1V + (((unsigned)kt^lm_koff)<<5));
#pragma unroll
      for(int nt=0;nt<2;nt++){
        int n=w*16+nt*8+gid;
        float2 bf=g_W2Vp[(n*16+kt)*4+tig];
        mma8(DV[nt][0],DV[nt][1],DV[nt][2],DV[nt][3],a0,a1,a2,a3,F2U(bf.x),F2U(bf.y));
      }
    }
#pragma unroll
    for(int nt=0;nt<2;nt++){
      int c0=w*16+nt*8+tig*2;
      float bv0=__ldg(b2V+c0),bv1=__ldg(b2V+c0+1),w30=__ldg(W3V+c0),w31=__ldg(W3V+c0+1);
      *(float2*)&sm[S_R2+swz(gid,c0)]  =make_float2(rna(w30*sg_f(DV[nt][0]+bv0)),rna(w31*sg_f(DV[nt][1]+bv1)));
      *(float2*)&sm[S_R2+swz(gid+8,c0)]=make_float2(rna(w30*sg_f(DV[nt][2]+bv0)),rna(w31*sg_f(DV[nt][3]+bv1)));
    }
    float D[8][2][4]={};
#pragma unroll 2
    for(int kt=0;kt<16;kt++){
      float2 bf[2];
#pragma unroll
      for(int nt=0;nt<2;nt++){ int n=w*16+nt*8+gid; bf[nt]=g_W2Lp[(n*16+kt)*4+tig]; }
      unsigned koff5=(((unsigned)kt^lm_koff)<<5);
#pragma unroll
      for(int m=0;m<8;m++){
        unsigned a0,a1,a2,a3; ldsm4(a0,a1,a2,a3, base_H + m*8192 + koff5);
#pragma unroll
        for(int nt=0;nt<2;nt++)
          mma8(D[m][nt][0],D[m][nt][1],D[m][nt][2],D[m][nt][3],a0,a1,a2,a3,F2U(bf[nt].x),F2U(bf[nt].y));
      }
    }
    __syncthreads();   // all warps done reading H
    float bL0[2],bL1[2];
#pragma unroll
    for(int nt=0;nt<2;nt++){ int c0=w*16+nt*8+tig*2; bL0[nt]=__ldg(b2L+c0); bL1[nt]=__ldg(b2L+c0+1); }
#pragma unroll
    for(int m=0;m<8;m++)
#pragma unroll
      for(int nt=0;nt<2;nt++){
        float d0=D[m][nt][0],d1=D[m][nt][1],d2=D[m][nt][2],d3=D[m][nt][3];
        float z0=__shfl_sync(FULLMASK,d0,tig)+bL0[nt], z1=__shfl_sync(FULLMASK,d1,tig)+bL1[nt];
        float z2=__shfl_sync(FULLMASK,d2,tig)+bL0[nt], z3=__shfl_sync(FULLMASK,d3,tig)+bL1[nt];
        int c0=w*16+nt*8+tig*2;
        float o0,o1,o2,o3;
        if (gid==0){ o0=sp_f(z0);o1=sp_f(z1);o2=sp_f(z2);o3=sp_f(z3); }
        else if (gid<7){ o0=sg_f(z0)*d0;o1=sg_f(z1)*d1;o2=sg_f(z2)*d2;o3=sg_f(z3)*d3; }
        else { o0=0.f;o1=0.f;o2=0.f;o3=0.f; }
        *(float2*)&sm[S_H+swz(m*16+gid,c0)]  =make_float2(rna(o0),rna(o1));
        *(float2*)&sm[S_H+swz(m*16+8+gid,c0)]=make_float2(rna(o2),rna(o3));
      }
  }
  __syncthreads();

  // ---------- P3: L layer3 (w0-2) | V backward (w4-7, 32 cols each: R5-verified shape) ----------
  if (w<3){
    float D3[8][4]={};
#pragma unroll 4
    for(int kt=0;kt<16;kt++){
      float2 bf=g_W3L24[((w*8+gid)*16+kt)*4+tig];
      unsigned koff5=(((unsigned)kt^lm_koff)<<5);
#pragma unroll
      for(int m=0;m<8;m++){
        unsigned a0,a1,a2,a3; ldsm4(a0,a1,a2,a3, base_H + m*8192 + koff5);
        mma8(D3[m][0],D3[m][1],D3[m][2],D3[m][3],a0,a1,a2,a3,F2U(bf.x),F2U(bf.y));
      }
    }
    int c0=w*8+tig*2;
    float bb0=(c0<21)?__ldg(b3L+c0):0.f, bb1=(c0+1<21)?__ldg(b3L+c0+1):0.f;
#pragma unroll
    for(int m=0;m<8;m++){
      float d0=D3[m][0],d1=D3[m][1],d2=D3[m][2],d3=D3[m][3];
      float z0=__shfl_sync(FULLMASK,d0,tig)+bb0, z1=__shfl_sync(FULLMASK,d1,tig)+bb1;
      float z2=__shfl_sync(FULLMASK,d2,tig)+bb0, z3=__shfl_sync(FULLMASK,d3,tig)+bb1;
      float o0,o1,o2,o3;
      if (gid==0){ o0=sp_f(z0);o1=sp_f(z1);o2=sp_f(z2);o3=sp_f(z3); }
      else if (gid<7){ o0=sg_f(z0)*d0;o1=sg_f(z1)*d1;o2=sg_f(z2)*d2;o3=sg_f(z3)*d3; }
      else { o0=0.f;o1=0.f;o2=0.f;o3=0.f; }
      sm[S_SL+(2*m)*200+gid*25+c0]=o0;   sm[S_SL+(2*m)*200+gid*25+c0+1]=o1;
      sm[S_SL+(2*m+1)*200+gid*25+c0]=o2; sm[S_SL+(2*m+1)*200+gid*25+c0+1]=o3;
    }
  } else if (w>=4){
    float D[4][4]={};
#pragma unroll 2
    for(int kt=0;kt<16;kt++){
      unsigned a0,a1,a2,a3; ldsm4(a0,a1,a2,a3, base_R2 + (((unsigned)kt^lm_koff)<<5));
#pragma unroll
      for(int nt=0;nt<4;nt++){
        int n=(w-4)*32+nt*8+gid;
        float2 bf=g_W2VT[(n*16+kt)*4+tig];
        mma8(D[nt][0],D[nt][1],D[nt][2],D[nt][3],a0,a1,a2,a3,F2U(bf.x),F2U(bf.y));
      }
    }
#pragma unroll
    for(int nt=0;nt<4;nt++){
      int c0=(w-4)*32+nt*8+tig*2;
      float2 hA=*(float2*)&sm[S_H1V+swz(gid,c0)];
      float2 hB=*(float2*)&sm[S_H1V+swz(gid+8,c0)];
      float r0=D[nt][0]*(1.f-__expf(-hA.x)), r1=D[nt][1]*(1.f-__expf(-hA.y));
      float r2=D[nt][2]*(1.f-__expf(-hB.x)), r3=D[nt][3]*(1.f-__expf(-hB.y));
      *(float2*)&sm[S_H1V+swz(gid,c0)]  =make_float2(rna(r0),rna(r1));
      *(float2*)&sm[S_H1V+swz(gid+8,c0)]=make_float2(rna(r2),rna(r3));
    }
  }
  __syncthreads();

  // ---------- P4: grad = r1 @ W1V^T (warp 0) ----------
  if (w==0){
    float D[2][4]={};
#pragma unroll 4
    for(int kt=0;kt<16;kt++){
      unsigned a0,a1,a2,a3; ldsm4(a0,a1,a2,a3, base_H1V + (((unsigned)kt^lm_koff)<<5));
#pragma unroll
      for(int nt=0;nt<2;nt++){
        int n=nt*8+gid;
        float2 bf=g_W1VT16[(n*16+kt)*4+tig];
        mma8(D[nt][0],D[nt][1],D[nt][2],D[nt][3],a0,a1,a2,a3,F2U(bf.x),F2U(bf.y));
      }
    }
#pragma unroll
    for(int nt=0;nt<2;nt++){
      int c=nt*8+tig*2;
      if (c<12){ sm[S_SG+gid*12+c]=D[nt][0]; sm[S_SG+(gid+8)*12+c]=D[nt][2]; }
      if (c+1<12){ sm[S_SG+gid*12+c+1]=D[nt][1]; sm[S_SG+(gid+8)*12+c+1]=D[nt][3]; }
    }
  }
  __syncthreads();

  // ---------- P5: assembly + Cholesky solve (warps 0-3, 8 lanes/element) ----------
  if (w<4){
    int gl=lane&7, grp=lane>>3, eloc=w*4+grp;
    int e=eb+eloc; bool valid=(e<B); if(!valid) e=B-1;
    const float* SLe=sm+S_SL+eloc*200;
    float* SDel=sm+S_H0+eloc*24;
    float qd6[6];
#pragma unroll
    for(int j=0;j<6;j++) qd6[j]=g_qds[S][e*6+j];
    if (gl<7){
#pragma unroll
      for(int t=0;t<3;t++){
        int m=gl*3+t;
        if (m<21){
          float s=0.f;
#pragma unroll
          for(int p=0;p<6;p++) s+=qd6[p]*SLe[(1+p)*25+m];
          SDel[m]=s;
        }
      }
    }
    __syncwarp();
    int li=(gl<6)?gl:5;
    float w6[6],u6[6],Dq[6];
#pragma unroll
    for(int k=0;k<6;k++){
      float sw=0.f,su=0.f,sd=0.f;
#pragma unroll
      for(int i2=0;i2<6;i2++) if (i2>=k){
        int m=TRI(i2,k); float a=qd6[i2];
        sw+=SLe[m]*a; su+=SLe[(1+li)*25+m]*a; sd+=SDel[m]*a;
      }
      w6[k]=sw; u6[k]=su; Dq[k]=sd;
    }
    float term2=0.f;
#pragma unroll
    for(int k=0;k<6;k++) term2+=w6[k]*u6[k];
    int base=li*(li+1)/2;
    float Dw=0.f,LDq=0.f;
#pragma unroll
    for(int j2=0;j2<6;j2++) if (j2<=li){ Dw+=SDel[base+j2]*w6[j2]; LDq+=SLe[base+j2]*Dq[j2]; }
    float ci=Dw+LDq-term2;
    float qsi=g_qs[S][e*6+li];
    float gi=-sm[S_SG+eloc*12+2*li]*sinf(qsi)+sm[S_SG+eloc*12+2*li+1]*cosf(qsi);
    float lo=c_LOWER[li]+0.1f, up=c_UPPER[li]-0.1f;
    float fi;
    if ((vm>>li)&1) fi=(qsi<=lo)?c_EFFORT[li]:((qsi>=up)?-c_EFFORT[li]:0.f);
    else            fi=-5.f*(1.f/(qsi-lo)-1.f/(up-qsi));
    float tau=__ldg(action+e*6+li)*c_EFFORT[li];
    float rhs=tau-ci-gi-fi;
    int gb=lane&~7;
    float accf=rhs, yvv=0.f;
#pragma unroll
    for(int j2=0;j2<6;j2++){
      float yj=__shfl_sync(FULLMASK,accf,gb+j2)/SLe[TRI(j2,j2)];
      if (gl==j2) yvv=yj;
      if (gl>j2 && gl<6) accf-=SLe[base+j2]*yj;
    }
    float acc2=yvv, xi=0.f;
#pragma unroll
    for(int j2=5;j2>=0;j2--){
      float xj=__shfl_sync(FULLMASK,acc2,gb+j2)/SLe[TRI(j2,j2)];
      if (gl==j2) xi=xj;
      if (gl<j2) acc2-=SLe[TRI(j2,gl)]*xj;
    }

    // ---- fused prep (stages 0-2) / fused final (stage 3) ----
    if (S<3){
      if (gl<6 && valid) g_kqd[S][e*6+gl]=xi;
      unsigned bits=0;
      if (gl<6 && valid){
        float q0=obs[e*12+gl], qd0=obs[e*12+6+gl];
        float qs,qds;
        if (S==0){ qs=q0+0.5f*DT*qd0;                 qds=qd0+0.5f*DT*xi; }
        else if (S==1){ qs=q0+0.5f*DT*g_qds[1][e*6+gl]; qds=qd0+0.5f*DT*xi; }
        else          { qs=q0+DT*g_qds[2][e*6+gl];      qds=qd0+DT*xi; }
        g_qs[S+1][e*6+gl]=qs; g_qds[S+1][e*6+gl]=qds;
        float lo2=c_LOWER[gl]+0.1f, up2=c_UPPER[gl]-0.1f;
        if (qs<=lo2 || qs>=up2) bits=1u<<gl;
      }
      unsigned r=__reduce_or_sync(FULLMASK,bits);
      if (lane==0 && r) atomicOr(&g_viol[S+1],(int)r);
    } else {
      if (gl<6 && valid){
        int idx=e*6+gl;
        float q0=obs[e*12+gl], qd0=obs[e*12+6+gl];
        float k0=g_kqd[0][idx],k1=g_kqd[1][idx],k2=g_kqd[2][idx];
        const float c1=DT/6.f;
        float qn=q0+c1*(g_qds[0][idx]+2.f*g_qds[1][idx]+2.f*g_qds[2][idx]+g_qds[3][idx]);
        qn=fminf(fmaxf(qn,c_LOWER[gl]),c_UPPER[gl]);
        float qdn=qd0+c1*(k0+2.f*k1+2.f*k2+xi);
        out[e*12+gl]=qn;
        out[e*12+6+gl]=qdn;
      }
    }
  }
}

extern "C" void kernel_launch(void* const* d_in, const int* in_sizes, int n_in,
                              void* d_out, int out_size)
{
  const float* obs   =(const float*)d_in[0];
  const float* action=(const float*)d_in[1];
  const float* W1L=(const float*)d_in[2];  const float* b1L=(const float*)d_in[3];
  const float* W2L=(const float*)d_in[4];  const float* b2L=(const float*)d_in[5];
  const float* W3L=(const float*)d_in[6];  const float* b3L=(const float*)d_in[7];
  const float* W1V=(const float*)d_in[8];  const float* b1V=(const float*)d_in[9];
  const float* W2V=(const float*)d_in[10]; const float* b2V=(const float*)d_in[11];
  const float* W3V=(const float*)d_in[12]; const float* b3V=(const float*)d_in[13];
  (void)b3V;
  float* out=(float*)d_out;
  int B=in_sizes[0]/12;
  if (B>MAXB) B=MAXB;

  cudaFuncSetAttribute(accel_mma_kernel, cudaFuncAttributeMaxDynamicSharedMemorySize, SMEM_FLOATS*4);

  int nbA=(B+15)/16;
  int nbI=(B*6+255)/256; if (nbI<114) nbI=114;

  zero_viol_kernel<<<1,32>>>();
  init_kernel<<<nbI,256>>>(obs,W1L,b1L,W2L,W3L,W1V,b1V,W2V,B);
  for (int s=0;s<4;s++){
    accel_mma_kernel<<<nbA,256,SMEM_FLOATS*4>>>(s,obs,action,out,b2L,b3L,b2V,W3V,B);
  }
}

// round 12
// speedup vs baseline: 1.5669x; 1.3718x over previous
#include <cuda_runtime.h>
#include <cuda_fp16.h>
#include <math.h>

#define MAXB 16384
#define DT 0.01f
#define FULLMASK 0xffffffffu
#define TRI(i,j) ((i)*((i)+1)/2+(j))

__constant__ float c_LOWER[6] = {-6.28f,-6.28f,-3.14f,-6.28f,-6.28f,-6.28f};
__constant__ float c_UPPER[6] = { 6.28f, 6.28f, 3.14f, 6.28f, 6.28f, 6.28f};
__constant__ float c_EFFORT[6]= {150.f,150.f,150.f,28.f,28.f,28.f};

__device__ float g_qs [4][MAXB*6];
__device__ float g_qds[4][MAXB*6];
__device__ float g_kqd[3][MAXB*6];
__device__ int   g_viol[4];

// fp16 B fragments for mma.m16n8k16: uint2 = {half2(W[n][k0],W[n][k0+1]), half2(W[n][k0+8],W[n][k0+9])}, k0=ktp*16+2*tig
__device__ uint2 g_W1L [128*4];      // K=16 (bias folded into col 12)
__device__ uint2 g_W2L [128*8*4];
__device__ uint2 g_W3L [24*8*4];
__device__ uint2 g_W1V [128*4];
__device__ uint2 g_W2V [128*8*4];
__device__ uint2 g_W2VT[128*8*4];
__device__ uint2 g_W1VT[16*8*4];

__device__ __forceinline__ float sp_f(float x){ return fmaxf(x,0.f)+__logf(1.f+__expf(-fabsf(x))); }
__device__ __forceinline__ float sg_f(float x){ return __fdividef(1.f,1.f+__expf(-x)); }
__device__ __forceinline__ void mma16(float*d,unsigned a0,unsigned a1,unsigned a2,unsigned a3,unsigned b0,unsigned b1){
  asm volatile("mma.sync.aligned.m16n8k16.row.col.f32.f16.f16.f32 "
    "{%0,%1,%2,%3},{%4,%5,%6,%7},{%8,%9},{%0,%1,%2,%3};"
    :"+f"(d[0]),"+f"(d[1]),"+f"(d[2]),"+f"(d[3])
    :"r"(a0),"r"(a1),"r"(a2),"r"(a3),"r"(b0),"r"(b1));
}
__device__ __forceinline__ void ldsm4(unsigned&r0,unsigned&r1,unsigned&r2,unsigned&r3,unsigned a){
  asm volatile("ldmatrix.sync.aligned.m8n8.x4.shared.b16 {%0,%1,%2,%3},[%4];"
    :"=r"(r0),"=r"(r1),"=r"(r2),"=r"(r3):"r"(a));
}
// 128-half rows (256B stride), 16B-segment XOR swizzle
__device__ __forceinline__ int hswz(int r,int c){ return r*256 + ((((c>>3)^(r&7)))<<4) + ((c&7)<<1); }
__device__ __forceinline__ uint2 packb(float a,float b,float c,float d){
  __half2 h0=__floats2half2_rn(a,b), h1=__floats2half2_rn(c,d);
  uint2 u; u.x=*(unsigned*)&h0; u.y=*(unsigned*)&h1; return u;
}

__global__ void zero_viol_kernel(){ if (threadIdx.x<4) g_viol[threadIdx.x]=0; }

// weights prep + stage-0 kinematics + viol[0]
__global__ void init_kernel(const float* __restrict__ obs,
    const float* __restrict__ W1L,const float* __restrict__ b1L,
    const float* __restrict__ W2L,const float* __restrict__ W3L,
    const float* __restrict__ W1V,const float* __restrict__ b1V,const float* __restrict__ W2V,
    int B){
  int i=blockIdx.x*blockDim.x+threadIdx.x;
  if (i<512){
    int n=i>>2, tig=i&3; int k0=2*tig;
    int ks[4]={k0,k0+1,k0+8,k0+9}; float v[4];
#pragma unroll
    for(int t=0;t<4;t++){ int k=ks[t]; v[t]=(k<12)?W1L[n*12+k]:((k==12)?b1L[n]:0.f); }
    g_W1L[i]=packb(v[0],v[1],v[2],v[3]);
  } else if (i<4608){ int j=i-512; int n=j>>5, ktp=(j>>2)&7, tig=j&3; int k0=ktp*16+2*tig;
    g_W2L[j]=packb(W2L[n*128+k0],W2L[n*128+k0+1],W2L[n*128+k0+8],W2L[n*128+k0+9]);
  } else if (i<5376){ int j=i-4608; int n=j>>5, ktp=(j>>2)&7, tig=j&3; int k0=ktp*16+2*tig;
    if (n<21) g_W3L[j]=packb(W3L[n*128+k0],W3L[n*128+k0+1],W3L[n*128+k0+8],W3L[n*128+k0+9]);
    else      g_W3L[j]=packb(0.f,0.f,0.f,0.f);
  } else if (i<5888){ int j=i-5376;
    int n=j>>2, tig=j&3; int k0=2*tig;
    int ks[4]={k0,k0+1,k0+8,k0+9}; float v[4];
#pragma unroll
    for(int t=0;t<4;t++){ int k=ks[t]; v[t]=(k<12)?W1V[n*12+k]:((k==12)?b1V[n]:0.f); }
    g_W1V[j]=packb(v[0],v[1],v[2],v[3]);
  } else if (i<9984){ int j=i-5888; int n=j>>5, ktp=(j>>2)&7, tig=j&3; int k0=ktp*16+2*tig;
    g_W2V[j]=packb(W2V[n*128+k0],W2V[n*128+k0+1],W2V[n*128+k0+8],W2V[n*128+k0+9]);
  } else if (i<14080){ int j=i-9984; int n=j>>5, ktp=(j>>2)&7, tig=j&3; int k0=ktp*16+2*tig;
    g_W2VT[j]=packb(W2V[k0*128+n],W2V[(k0+1)*128+n],W2V[(k0+8)*128+n],W2V[(k0+9)*128+n]);
  } else if (i<14592){ int j=i-14080; int n=j>>5, ktp=(j>>2)&7, tig=j&3; int k0=ktp*16+2*tig;
    if (n<12) g_W1VT[j]=packb(W1V[k0*12+n],W1V[(k0+1)*12+n],W1V[(k0+8)*12+n],W1V[(k0+9)*12+n]);
    else      g_W1VT[j]=packb(0.f,0.f,0.f,0.f);
  }
  unsigned b0=0;
  if (i<B*6){
    int e=i/6, j=i-e*6;
    float q0=obs[e*12+j], qd0=obs[e*12+6+j];
    g_qs[0][i]=q0; g_qds[0][i]=qd0;
    float lo=c_LOWER[j]+0.1f, up=c_UPPER[j]-0.1f;
    if (q0<=lo || q0>=up) b0=1u<<j;
  }
  unsigned r0=__reduce_or_sync(FULLMASK,b0);
  if ((threadIdx.x&31)==0 && r0) atomicOr(&g_viol[0],(int)r0);
}

// smem layout (bytes). half regions: A0 (128 rows x 24 halves = 48B rows),
// VIN (16 x 48B), H / H1V / R2 (swizzled 256B rows). float regions: SL, SG.
#define BA0   0
#define BVIN  6144
#define BH    7168
#define BH1V  39936
#define BR2   44032
#define BSL   48128
#define BSG   59392
#define SMEM_BYTES 60160
#define WSL (BSL/4)
#define WSG (BSG/4)

__global__ void __launch_bounds__(256,2)
accel_mma_kernel(int S, const float* __restrict__ obs, const float* __restrict__ action,
    float* __restrict__ out,
    const float* __restrict__ b2L, const float* __restrict__ b3L,
    const float* __restrict__ b2V, const float* __restrict__ W3V, int B)
{
  extern __shared__ char smc[];
  float* smf=(float*)smc;
  const int tid=threadIdx.x, w=tid>>5, lane=tid&31;
  const int gid=lane>>2, tig=lane&3;
  const int eb=blockIdx.x*16;
  const int vm=g_viol[S];
  const unsigned smb=(unsigned)__cvta_generic_to_shared(smc);

  // ldmatrix lane addressing
  const int sub=lane>>3, l7=lane&7;
  const int lm_row=l7+((sub&1)<<3);
  const int chunk=sub>>1;            // 0: k0-7, 1: k8-15
  const int r7=l7;
  const unsigned aA0 = smb + BA0 + lm_row*48 + chunk*16;
  const unsigned aVIN= smb + BVIN + lm_row*48 + chunk*16;
  const unsigned rbH  = smb + BH   + lm_row*256;
  const unsigned rbH1V= smb + BH1V + lm_row*256;
  const unsigned rbR2 = smb + BR2  + lm_row*256;

  // ---------- P0: build A matrices ----------
  if (tid<128){
    int row=tid, ch=row&7, el=row>>3;
    int e=eb+el; if (e>=B) e=B-1;
    float t16[16];
#pragma unroll
    for(int k=0;k<16;k++) t16[k]=0.f;
    if (ch==0){
#pragma unroll
      for(int j=0;j<6;j++){ float qj=g_qs[S][e*6+j]; t16[2*j]=cosf(qj); t16[2*j+1]=sinf(qj); }
      t16[12]=1.f;
    } else if (ch<7){
      int p=ch-1; float qp=g_qs[S][e*6+p];
      t16[2*p]=-sinf(qp); t16[2*p+1]=cosf(qp);
    }
    __half2* dst=(__half2*)(smc+BA0+row*48);
#pragma unroll
    for(int k=0;k<8;k++) dst[k]=__floats2half2_rn(t16[2*k],t16[2*k+1]);
    if (ch==0){
      __half2* dv=(__half2*)(smc+BVIN+el*48);
#pragma unroll
      for(int k=0;k<8;k++) dv[k]=__floats2half2_rn(t16[2*k],t16[2*k+1]);
    }
  }
  __syncthreads();

  // ---------- P1: V layer1 + L layer1 (one K=16 mma each) ----------
  {
    float DV[2][4]={};
    {
      unsigned a0,a1,a2,a3; ldsm4(a0,a1,a2,a3,aVIN);
#pragma unroll
      for(int nt=0;nt<2;nt++){
        uint2 bf=__ldg(&g_W1V[(w*16+nt*8+gid)*4+tig]);
        mma16(DV[nt],a0,a1,a2,a3,bf.x,bf.y);
      }
    }
#pragma unroll
    for(int nt=0;nt<2;nt++){
      int c0=w*16+nt*8+tig*2;
      *(__half2*)(smc+BH1V+hswz(gid,c0))  =__floats2half2_rn(sp_f(DV[nt][0]),sp_f(DV[nt][1]));
      *(__half2*)(smc+BH1V+hswz(gid+8,c0))=__floats2half2_rn(sp_f(DV[nt][2]),sp_f(DV[nt][3]));
    }
    float D1[8][2][4]={};
#pragma unroll
    for(int m=0;m<8;m++){
      unsigned a0,a1,a2,a3; ldsm4(a0,a1,a2,a3,aA0+m*768);
#pragma unroll
      for(int nt=0;nt<2;nt++){
        uint2 bf=__ldg(&g_W1L[(w*16+nt*8+gid)*4+tig]);
        mma16(D1[m][nt],a0,a1,a2,a3,bf.x,bf.y);
      }
    }
#pragma unroll
    for(int m=0;m<8;m++)
#pragma unroll
      for(int nt=0;nt<2;nt++){
        float d0=D1[m][nt][0],d1=D1[m][nt][1],d2=D1[m][nt][2],d3=D1[m][nt][3];
        float z0=__shfl_sync(FULLMASK,d0,tig), z1=__shfl_sync(FULLMASK,d1,tig);
        float z2=__shfl_sync(FULLMASK,d2,tig), z3=__shfl_sync(FULLMASK,d3,tig);
        int c0=w*16+nt*8+tig*2;
        float o0,o1,o2,o3;
        if (gid==0){ o0=sp_f(z0);o1=sp_f(z1);o2=sp_f(z2);o3=sp_f(z3); }
        else if (gid<7){ o0=sg_f(z0)*d0;o1=sg_f(z1)*d1;o2=sg_f(z2)*d2;o3=sg_f(z3)*d3; }
        else { o0=0.f;o1=0.f;o2=0.f;o3=0.f; }
        *(__half2*)(smc+BH+hswz(m*16+gid,c0))  =__floats2half2_rn(o0,o1);
        *(__half2*)(smc+BH+hswz(m*16+8+gid,c0))=__floats2half2_rn(o2,o3);
      }
  }
  __syncthreads();

  // ---------- P2: V layer2 + L layer2 (in place on H) ----------
  {
    float DV[2][4]={};
#pragma unroll
    for(int ktp=0;ktp<8;ktp++){
      unsigned a0,a1,a2,a3; ldsm4(a0,a1,a2,a3, rbH1V + (((2*ktp+chunk)^r7)<<4));
#pragma unroll
      for(int nt=0;nt<2;nt++){
        uint2 bf=__ldg(&g_W2V[((w*16+nt*8+gid)*8+ktp)*4+tig]);
        mma16(DV[nt],a0,a1,a2,a3,bf.x,bf.y);
      }
    }
#pragma unroll
    for(int nt=0;nt<2;nt++){
      int c0=w*16+nt*8+tig*2;
      float bv0=__ldg(b2V+c0),bv1=__ldg(b2V+c0+1),w30=__ldg(W3V+c0),w31=__ldg(W3V+c0+1);
      *(__half2*)(smc+BR2+hswz(gid,c0))  =__floats2half2_rn(w30*sg_f(DV[nt][0]+bv0),w31*sg_f(DV[nt][1]+bv1));
      *(__half2*)(smc+BR2+hswz(gid+8,c0))=__floats2half2_rn(w30*sg_f(DV[nt][2]+bv0),w31*sg_f(DV[nt][3]+bv1));
    }
    float D2[8][2][4]={};
#pragma unroll 2
    for(int ktp=0;ktp<8;ktp++){
      uint2 bf[2];
#pragma unroll
      for(int nt=0;nt<2;nt++) bf[nt]=__ldg(&g_W2L[((w*16+nt*8+gid)*8+ktp)*4+tig]);
      unsigned koff=(((unsigned)(2*ktp+chunk)^r7)<<4);
#pragma unroll
      for(int m=0;m<8;m++){
        unsigned a0,a1,a2,a3; ldsm4(a0,a1,a2,a3, rbH + m*4096 + koff);
#pragma unroll
        for(int nt=0;nt<2;nt++) mma16(D2[m][nt],a0,a1,a2,a3,bf[nt].x,bf[nt].y);
      }
    }
    __syncthreads();   // all warps done reading H
    float bL0[2],bL1[2];
#pragma unroll
    for(int nt=0;nt<2;nt++){ int c0=w*16+nt*8+tig*2; bL0[nt]=__ldg(b2L+c0); bL1[nt]=__ldg(b2L+c0+1); }
#pragma unroll
    for(int m=0;m<8;m++)
#pragma unroll
      for(int nt=0;nt<2;nt++){
        float d0=D2[m][nt][0],d1=D2[m][nt][1],d2=D2[m][nt][2],d3=D2[m][nt][3];
        float z0=__shfl_sync(FULLMASK,d0,tig)+bL0[nt], z1=__shfl_sync(FULLMASK,d1,tig)+bL1[nt];
        float z2=__shfl_sync(FULLMASK,d2,tig)+bL0[nt], z3=__shfl_sync(FULLMASK,d3,tig)+bL1[nt];
        int c0=w*16+nt*8+tig*2;
        float o0,o1,o2,o3;
        if (gid==0){ o0=sp_f(z0);o1=sp_f(z1);o2=sp_f(z2);o3=sp_f(z3); }
        else if (gid<7){ o0=sg_f(z0)*d0;o1=sg_f(z1)*d1;o2=sg_f(z2)*d2;o3=sg_f(z3)*d3; }
        else { o0=0.f;o1=0.f;o2=0.f;o3=0.f; }
        *(__half2*)(smc+BH+hswz(m*16+gid,c0))  =__floats2half2_rn(o0,o1);
        *(__half2*)(smc+BH+hswz(m*16+8+gid,c0))=__floats2half2_rn(o2,o3);
      }
  }
  __syncthreads();

  // ---------- P3: L layer3 (w0-2) | V backward (w4-7, 32 cols each: verified R5 shape) ----------
  if (w<3){
    float D3[8][4]={};
#pragma unroll 2
    for(int ktp=0;ktp<8;ktp++){
      uint2 bf=__ldg(&g_W3L[((w*8+gid)*8+ktp)*4+tig]);
      unsigned koff=(((unsigned)(2*ktp+chunk)^r7)<<4);
#pragma unroll
      for(int m=0;m<8;m++){
        unsigned a0,a1,a2,a3; ldsm4(a0,a1,a2,a3, rbH + m*4096 + koff);
        mma16(D3[m],a0,a1,a2,a3,bf.x,bf.y);
      }
    }
    int c0=w*8+tig*2;
    float bb0=(c0<21)?__ldg(b3L+c0):0.f, bb1=(c0+1<21)?__ldg(b3L+c0+1):0.f;
#pragma unroll
    for(int m=0;m<8;m++){
      float d0=D3[m][0],d1=D3[m][1],d2=D3[m][2],d3=D3[m][3];
      float z0=__shfl_sync(FULLMASK,d0,tig)+bb0, z1=__shfl_sync(FULLMASK,d1,tig)+bb1;
      float z2=__shfl_sync(FULLMASK,d2,tig)+bb0, z3=__shfl_sync(FULLMASK,d3,tig)+bb1;
      if (gid<7){     // gid==7 = padding channel; SL stride is 176 floats
        float o0,o1,o2,o3;
        if (gid==0){ o0=sp_f(z0);o1=sp_f(z1);o2=sp_f(z2);o3=sp_f(z3); }
        else { o0=sg_f(z0)*d0;o1=sg_f(z1)*d1;o2=sg_f(z2)*d2;o3=sg_f(z3)*d3; }
        smf[WSL+(2*m)*176+gid*25+c0]=o0;   smf[WSL+(2*m)*176+gid*25+c0+1]=o1;
        smf[WSL+(2*m+1)*176+gid*25+c0]=o2; smf[WSL+(2*m+1)*176+gid*25+c0+1]=o3;
      }
    }
  } else if (w>=4){
    float DB[4][4]={};
#pragma unroll 2
    for(int ktp=0;ktp<8;ktp++){
      unsigned a0,a1,a2,a3; ldsm4(a0,a1,a2,a3, rbR2 + (((2*ktp+chunk)^r7)<<4));
#pragma unroll
      for(int nt=0;nt<4;nt++){
        int n=(w-4)*32+nt*8+gid;
        uint2 bf=__ldg(&g_W2VT[(n*8+ktp)*4+tig]);
        mma16(DB[nt],a0,a1,a2,a3,bf.x,bf.y);
      }
    }
#pragma unroll
    for(int nt=0;nt<4;nt++){
      int c0=(w-4)*32+nt*8+tig*2;
      float2 hA=__half22float2(*(__half2*)(smc+BH1V+hswz(gid,c0)));
      float2 hB=__half22float2(*(__half2*)(smc+BH1V+hswz(gid+8,c0)));
      float r0=DB[nt][0]*(1.f-__expf(-hA.x)), r1=DB[nt][1]*(1.f-__expf(-hA.y));
      float r2=DB[nt][2]*(1.f-__expf(-hB.x)), r3=DB[nt][3]*(1.f-__expf(-hB.y));
      *(__half2*)(smc+BH1V+hswz(gid,c0))  =__floats2half2_rn(r0,r1);
      *(__half2*)(smc+BH1V+hswz(gid+8,c0))=__floats2half2_rn(r2,r3);
    }
  }
  __syncthreads();

  // ---------- P4: grad = r1 @ W1V (warp 0) ----------
  if (w==0){
    float DG[2][4]={};
#pragma unroll 2
    for(int ktp=0;ktp<8;ktp++){
      unsigned a0,a1,a2,a3; ldsm4(a0,a1,a2,a3, rbH1V + (((2*ktp+chunk)^r7)<<4));
#pragma unroll
      for(int nt=0;nt<2;nt++){
        uint2 bf=__ldg(&g_W1VT[((nt*8+gid)*8+ktp)*4+tig]);
        mma16(DG[nt],a0,a1,a2,a3,bf.x,bf.y);
      }
    }
#pragma unroll
    for(int nt=0;nt<2;nt++){
      int c=nt*8+tig*2;
      if (c<12){ smf[WSG+gid*12+c]=DG[nt][0]; smf[WSG+(gid+8)*12+c]=DG[nt][2]; }
      if (c+1<12){ smf[WSG+gid*12+c+1]=DG[nt][1]; smf[WSG+(gid+8)*12+c+1]=DG[nt][3]; }
    }
  }
  __syncthreads();

  // ---------- P5: assembly + Cholesky solve (warps 0-3, 8 lanes/element) ----------
  if (w<4){
    int gl=lane&7, grp=lane>>3, eloc=w*4+grp;
    int e=eb+eloc; bool valid=(e<B); if(!valid) e=B-1;
    const float* SLe=smf+WSL+eloc*176;
    float* SDel=smf+eloc*24;          // reuse A0 region (floats)
    float qd6[6];
#pragma unroll
    for(int j=0;j<6;j++) qd6[j]=g_qds[S][e*6+j];
    if (gl<7){
#pragma unroll
      for(int t=0;t<3;t++){
        int m=gl*3+t;
        if (m<21){
          float s=0.f;
#pragma unroll
          for(int p=0;p<6;p++) s+=qd6[p]*SLe[(1+p)*25+m];
          SDel[m]=s;
        }
      }
    }
    __syncwarp();
    int li=(gl<6)?gl:5;
    float w6[6],u6[6],Dq[6];
#pragma unroll
    for(int k=0;k<6;k++){
      float sw=0.f,su=0.f,sd=0.f;
#pragma unroll
      for(int i2=0;i2<6;i2++) if (i2>=k){
        int m=TRI(i2,k); float a=qd6[i2];
        sw+=SLe[m]*a; su+=SLe[(1+li)*25+m]*a; sd+=SDel[m]*a;
      }
      w6[k]=sw; u6[k]=su; Dq[k]=sd;
    }
    float term2=0.f;
#pragma unroll
    for(int k=0;k<6;k++) term2+=w6[k]*u6[k];
    int base=li*(li+1)/2;
    float Dw=0.f,LDq=0.f;
#pragma unroll
    for(int j2=0;j2<6;j2++) if (j2<=li){ Dw+=SDel[base+j2]*w6[j2]; LDq+=SLe[base+j2]*Dq[j2]; }
    float ci=Dw+LDq-term2;
    float qsi=g_qs[S][e*6+li];
    float gi=-smf[WSG+eloc*12+2*li]*sinf(qsi)+smf[WSG+eloc*12+2*li+1]*cosf(qsi);
    float lo=c_LOWER[li]+0.1f, up=c_UPPER[li]-0.1f;
    float fi;
    if ((vm>>li)&1) fi=(qsi<=lo)?c_EFFORT[li]:((qsi>=up)?-c_EFFORT[li]:0.f);
    else            fi=-5.f*(1.f/(qsi-lo)-1.f/(up-qsi));
    float tau=__ldg(action+e*6+li)*c_EFFORT[li];
    float rhs=tau-ci-gi-fi;
    int gb=lane&~7;
    float accf=rhs, yvv=0.f;
#pragma unroll
    for(int j2=0;j2<6;j2++){
      float yj=__shfl_sync(FULLMASK,accf,gb+j2)/SLe[TRI(j2,j2)];
      if (gl==j2) yvv=yj;
      if (gl>j2 && gl<6) accf-=SLe[base+j2]*yj;
    }
    float acc2=yvv, xi=0.f;
#pragma unroll
    for(int j2=5;j2>=0;j2--){
      float xj=__shfl_sync(FULLMASK,acc2,gb+j2)/SLe[TRI(j2,j2)];
      if (gl==j2) xi=xj;
      if (gl<j2) acc2-=SLe[TRI(j2,gl)]*xj;
    }

    // ---- fused prep (stages 0-2) / fused final (stage 3) ----
    if (S<3){
      if (gl<6 && valid) g_kqd[S][e*6+gl]=xi;
      unsigned bits=0;
      if (gl<6 && valid){
        float q0=obs[e*12+gl], qd0=obs[e*12+6+gl];
        float qs,qds;
        if (S==0){ qs=q0+0.5f*DT*qd0;                 qds=qd0+0.5f*DT*xi; }
        else if (S==1){ qs=q0+0.5f*DT*g_qds[1][e*6+gl]; qds=qd0+0.5f*DT*xi; }
        else          { qs=q0+DT*g_qds[2][e*6+gl];      qds=qd0+DT*xi; }
        g_qs[S+1][e*6+gl]=qs; g_qds[S+1][e*6+gl]=qds;
        float lo2=c_LOWER[gl]+0.1f, up2=c_UPPER[gl]-0.1f;
        if (qs<=lo2 || qs>=up2) bits=1u<<gl;
      }
      unsigned r=__reduce_or_sync(FULLMASK,bits);
      if (lane==0 && r) atomicOr(&g_viol[S+1],(int)r);
    } else {
      if (gl<6 && valid){
        int idx=e*6+gl;
        float q0=obs[e*12+gl], qd0=obs[e*12+6+gl];
        float k0=g_kqd[0][idx],k1=g_kqd[1][idx],k2=g_kqd[2][idx];
        const float c1=DT/6.f;
        float qn=q0+c1*(g_qds[0][idx]+2.f*g_qds[1][idx]+2.f*g_qds[2][idx]+g_qds[3][idx]);
        qn=fminf(fmaxf(qn,c_LOWER[gl]),c_UPPER[gl]);
        float qdn=qd0+c1*(k0+2.f*k1+2.f*k2+xi);
        out[e*12+gl]=qn;
        out[e*12+6+gl]=qdn;
      }
    }
  }
}

extern "C" void kernel_launch(void* const* d_in, const int* in_sizes, int n_in,
                              void* d_out, int out_size)
{
  const float* obs   =(const float*)d_in[0];
  const float* action=(const float*)d_in[1];
  const float* W1L=(const float*)d_in[2];  const float* b1L=(const float*)d_in[3];
  const float* W2L=(const float*)d_in[4];  const float* b2L=(const float*)d_in[5];
  const float* W3L=(const float*)d_in[6];  const float* b3L=(const float*)d_in[7];
  const float* W1V=(const float*)d_in[8];  const float* b1V=(const float*)d_in[9];
  const float* W2V=(const float*)d_in[10]; const float* b2V=(const float*)d_in[11];
  const float* W3V=(const float*)d_in[12]; const float* b3V=(const float*)d_in[13];
  (void)b3V;
  float* out=(float*)d_out;
  int B=in_sizes[0]/12;
  if (B>MAXB) B=MAXB;

  cudaFuncSetAttribute(accel_mma_kernel, cudaFuncAttributeMaxDynamicSharedMemorySize, SMEM_BYTES);

  int nbA=(B+15)/16;
  int nbI=(B*6+255)/256; if (nbI<57) nbI=57;

  zero_viol_kernel<<<1,32>>>();
  init_kernel<<<nbI,256>>>(obs,W1L,b1L,W2L,W3L,W1V,b1V,W2V,B);
  for (int s=0;s<4;s++){
    accel_mma_kernel<<<nbA,256,SMEM_BYTES>>>(s,obs,action,out,b2L,b3L,b2V,W3V,B);
  }
}

// round 13
// speedup vs baseline: 2.6991x; 1.7225x over previous
#include <cuda_runtime.h>
#include <cuda_fp16.h>
#include <math.h>

#define MAXB 16384
#define DT 0.01f
#define FULLMASK 0xffffffffu
#define TRI(i,j) ((i)*((i)+1)/2+(j))

__constant__ float c_LOWER[6] = {-6.28f,-6.28f,-3.14f,-6.28f,-6.28f,-6.28f};
__constant__ float c_UPPER[6] = { 6.28f, 6.28f, 3.14f, 6.28f, 6.28f, 6.28f};
__constant__ float c_EFFORT[6]= {150.f,150.f,150.f,28.f,28.f,28.f};

__device__ float g_qs [4][MAXB*6];
__device__ float g_qds[4][MAXB*6];
__device__ float g_kqd[3][MAXB*6];
__device__ int   g_viol[4];

// fp16 B fragments for mma.m16n8k16
__device__ uint2 g_W1L [128*4];
__device__ uint2 g_W2L [128*8*4];
__device__ uint2 g_W3L [24*8*4];
__device__ uint2 g_W1V [128*4];
__device__ uint2 g_W2V [128*8*4];
__device__ uint2 g_W2VT[128*8*4];
__device__ uint2 g_W1VT[16*8*4];

__device__ __forceinline__ float sp_f(float x){ return fmaxf(x,0.f)+__logf(1.f+__expf(-fabsf(x))); }
__device__ __forceinline__ float sg_f(float x){ return __fdividef(1.f,1.f+__expf(-x)); }
__device__ __forceinline__ void mma16(float*d,unsigned a0,unsigned a1,unsigned a2,unsigned a3,unsigned b0,unsigned b1){
  asm volatile("mma.sync.aligned.m16n8k16.row.col.f32.f16.f16.f32 "
    "{%0,%1,%2,%3},{%4,%5,%6,%7},{%8,%9},{%0,%1,%2,%3};"
    :"+f"(d[0]),"+f"(d[1]),"+f"(d[2]),"+f"(d[3])
    :"r"(a0),"r"(a1),"r"(a2),"r"(a3),"r"(b0),"r"(b1));
}
__device__ __forceinline__ void ldsm4(unsigned&r0,unsigned&r1,unsigned&r2,unsigned&r3,unsigned a){
  asm volatile("ldmatrix.sync.aligned.m8n8.x4.shared.b16 {%0,%1,%2,%3},[%4];"
    :"=r"(r0),"=r"(r1),"=r"(r2),"=r"(r3):"r"(a));
}
// 128-half rows (256B stride), 16B-segment XOR swizzle
__device__ __forceinline__ int hswz(int r,int c){ return r*256 + ((((c>>3)^(r&7)))<<4) + ((c&7)<<1); }
__device__ __forceinline__ uint2 packb(float a,float b,float c,float d){
  __half2 h0=__floats2half2_rn(a,b), h1=__floats2half2_rn(c,d);
  uint2 u; u.x=*(unsigned*)&h0; u.y=*(unsigned*)&h1; return u;
}

__global__ void zero_viol_kernel(){ if (threadIdx.x<4) g_viol[threadIdx.x]=0; }

// weights prep + stage-0 kinematics + viol[0]
__global__ void init_kernel(const float* __restrict__ obs,
    const float* __restrict__ W1L,const float* __restrict__ b1L,
    const float* __restrict__ W2L,const float* __restrict__ W3L,
    const float* __restrict__ W1V,const float* __restrict__ b1V,const float* __restrict__ W2V,
    int B){
  int i=blockIdx.x*blockDim.x+threadIdx.x;
  if (i<512){
    int n=i>>2, tig=i&3; int k0=2*tig;
    int ks[4]={k0,k0+1,k0+8,k0+9}; float v[4];
#pragma unroll
    for(int t=0;t<4;t++){ int k=ks[t]; v[t]=(k<12)?W1L[n*12+k]:((k==12)?b1L[n]:0.f); }
    g_W1L[i]=packb(v[0],v[1],v[2],v[3]);
  } else if (i<4608){ int j=i-512; int n=j>>5, ktp=(j>>2)&7, tig=j&3; int k0=ktp*16+2*tig;
    g_W2L[j]=packb(W2L[n*128+k0],W2L[n*128+k0+1],W2L[n*128+k0+8],W2L[n*128+k0+9]);
  } else if (i<5376){ int j=i-4608; int n=j>>5, ktp=(j>>2)&7, tig=j&3; int k0=ktp*16+2*tig;
    if (n<21) g_W3L[j]=packb(W3L[n*128+k0],W3L[n*128+k0+1],W3L[n*128+k0+8],W3L[n*128+k0+9]);
    else      g_W3L[j]=packb(0.f,0.f,0.f,0.f);
  } else if (i<5888){ int j=i-5376;
    int n=j>>2, tig=j&3; int k0=2*tig;
    int ks[4]={k0,k0+1,k0+8,k0+9}; float v[4];
#pragma unroll
    for(int t=0;t<4;t++){ int k=ks[t]; v[t]=(k<12)?W1V[n*12+k]:((k==12)?b1V[n]:0.f); }
    g_W1V[j]=packb(v[0],v[1],v[2],v[3]);
  } else if (i<9984){ int j=i-5888; int n=j>>5, ktp=(j>>2)&7, tig=j&3; int k0=ktp*16+2*tig;
    g_W2V[j]=packb(W2V[n*128+k0],W2V[n*128+k0+1],W2V[n*128+k0+8],W2V[n*128+k0+9]);
  } else if (i<14080){ int j=i-9984; int n=j>>5, ktp=(j>>2)&7, tig=j&3; int k0=ktp*16+2*tig;
    g_W2VT[j]=packb(W2V[k0*128+n],W2V[(k0+1)*128+n],W2V[(k0+8)*128+n],W2V[(k0+9)*128+n]);
  } else if (i<14592){ int j=i-14080; int n=j>>5, ktp=(j>>2)&7, tig=j&3; int k0=ktp*16+2*tig;
    if (n<12) g_W1VT[j]=packb(W1V[k0*12+n],W1V[(k0+1)*12+n],W1V[(k0+8)*12+n],W1V[(k0+9)*12+n]);
    else      g_W1VT[j]=packb(0.f,0.f,0.f,0.f);
  }
  unsigned b0=0;
  if (i<B*6){
    int e=i/6, j=i-e*6;
    float q0=obs[e*12+j], qd0=obs[e*12+6+j];
    g_qs[0][i]=q0; g_qds[0][i]=qd0;
    float lo=c_LOWER[j]+0.1f, up=c_UPPER[j]-0.1f;
    if (q0<=lo || q0>=up) b0=1u<<j;
  }
  unsigned r0=__reduce_or_sync(FULLMASK,b0);
  if ((threadIdx.x&31)==0 && r0) atomicOr(&g_viol[0],(int)r0);
}

// smem layout (bytes). A0: 112 rows (row=ch*16+el) x 48B; VIN 16x48B;
// H 112x256B swizzled; H1V/R2 16x256B swizzled; SL/SG float regions.
#define BA0   0
#define BVIN  5376
#define BH    6144
#define BH1V  34816
#define BR2   38912
#define BSL   43008
#define BSG   54272
#define SMEM_BYTES 57344
#define WSL (BSL/4)
#define WSG (BSG/4)

__global__ void __launch_bounds__(256,2)
accel_mma_kernel(int S, const float* __restrict__ obs, const float* __restrict__ action,
    float* __restrict__ out,
    const float* __restrict__ b2L, const float* __restrict__ b3L,
    const float* __restrict__ b2V, const float* __restrict__ W3V, int B)
{
  extern __shared__ char smc[];
  float* smf=(float*)smc;
  const int tid=threadIdx.x, w=tid>>5, lane=tid&31;
  const int gid=lane>>2, tig=lane&3;
  const int eb=blockIdx.x*16;
  const int vm=g_viol[S];
  const unsigned smb=(unsigned)__cvta_generic_to_shared(smc);

  // ldmatrix lane addressing
  const int sub=lane>>3, l7=lane&7;
  const int lm_row=l7+((sub&1)<<3);
  const int chunk=sub>>1;
  const int r7=l7;
  const unsigned aA0 = smb + BA0 + lm_row*48 + chunk*16;
  const unsigned aVIN= smb + BVIN + lm_row*48 + chunk*16;
  const unsigned rbH  = smb + BH   + lm_row*256;
  const unsigned rbH1V= smb + BH1V + lm_row*256;
  const unsigned rbR2 = smb + BR2  + lm_row*256;

  // ---------- P0: build A matrices (row = ch*16 + el) ----------
  if (tid<112){
    int row=tid, ch=row>>4, el=row&15;
    int e=eb+el; if (e>=B) e=B-1;
    float t16[16];
#pragma unroll
    for(int k=0;k<16;k++) t16[k]=0.f;
    if (ch==0){
#pragma unroll
      for(int j=0;j<6;j++){ float qj=g_qs[S][e*6+j]; t16[2*j]=cosf(qj); t16[2*j+1]=sinf(qj); }
      t16[12]=1.f;
    } else {
      int p=ch-1; float qp=g_qs[S][e*6+p];
      t16[2*p]=-sinf(qp); t16[2*p+1]=cosf(qp);
    }
    __half2* dst=(__half2*)(smc+BA0+row*48);
#pragma unroll
    for(int k=0;k<8;k++) dst[k]=__floats2half2_rn(t16[2*k],t16[2*k+1]);
    if (ch==0){
      __half2* dv=(__half2*)(smc+BVIN+el*48);
#pragma unroll
      for(int k=0;k<8;k++) dv[k]=__floats2half2_rn(t16[2*k],t16[2*k+1]);
    }
  }
  __syncthreads();

  // ---------- P1: V layer1 + L layer1 (K=16) ----------
  {
    float DV[2][4]={};
    {
      unsigned a0,a1,a2,a3; ldsm4(a0,a1,a2,a3,aVIN);
#pragma unroll
      for(int nt=0;nt<2;nt++){
        uint2 bf=__ldg(&g_W1V[(w*16+nt*8+gid)*4+tig]);
        mma16(DV[nt],a0,a1,a2,a3,bf.x,bf.y);
      }
    }
#pragma unroll
    for(int nt=0;nt<2;nt++){
      int c0=w*16+nt*8+tig*2;
      *(__half2*)(smc+BH1V+hswz(gid,c0))  =__floats2half2_rn(sp_f(DV[nt][0]),sp_f(DV[nt][1]));
      *(__half2*)(smc+BH1V+hswz(gid+8,c0))=__floats2half2_rn(sp_f(DV[nt][2]),sp_f(DV[nt][3]));
    }
    float D1[7][2][4]={};
#pragma unroll
    for(int m=0;m<7;m++){
      unsigned a0,a1,a2,a3; ldsm4(a0,a1,a2,a3,aA0+m*768);
#pragma unroll
      for(int nt=0;nt<2;nt++){
        uint2 bf=__ldg(&g_W1L[(w*16+nt*8+gid)*4+tig]);
        mma16(D1[m][nt],a0,a1,a2,a3,bf.x,bf.y);
      }
    }
    // epilogue: tile 0 = fwd channel; sigmoid kept in registers
    float sgr[2][4];
#pragma unroll
    for(int nt=0;nt<2;nt++){
      int c0=w*16+nt*8+tig*2;
#pragma unroll
      for(int i=0;i<4;i++) sgr[nt][i]=sg_f(D1[0][nt][i]);
      *(__half2*)(smc+BH+hswz(gid,c0))  =__floats2half2_rn(sp_f(D1[0][nt][0]),sp_f(D1[0][nt][1]));
      *(__half2*)(smc+BH+hswz(gid+8,c0))=__floats2half2_rn(sp_f(D1[0][nt][2]),sp_f(D1[0][nt][3]));
    }
#pragma unroll
    for(int m=1;m<7;m++)
#pragma unroll
      for(int nt=0;nt<2;nt++){
        int c0=w*16+nt*8+tig*2;
        *(__half2*)(smc+BH+hswz(m*16+gid,c0))  =__floats2half2_rn(sgr[nt][0]*D1[m][nt][0],sgr[nt][1]*D1[m][nt][1]);
        *(__half2*)(smc+BH+hswz(m*16+8+gid,c0))=__floats2half2_rn(sgr[nt][2]*D1[m][nt][2],sgr[nt][3]*D1[m][nt][3]);
      }
  }
  __syncthreads();

  // ---------- P2: V layer2 + L layer2 (in place on H) ----------
  {
    float DV[2][4]={};
#pragma unroll
    for(int ktp=0;ktp<8;ktp++){
      unsigned a0,a1,a2,a3; ldsm4(a0,a1,a2,a3, rbH1V + (((2*ktp+chunk)^r7)<<4));
#pragma unroll
      for(int nt=0;nt<2;nt++){
        uint2 bf=__ldg(&g_W2V[((w*16+nt*8+gid)*8+ktp)*4+tig]);
        mma16(DV[nt],a0,a1,a2,a3,bf.x,bf.y);
      }
    }
#pragma unroll
    for(int nt=0;nt<2;nt++){
      int c0=w*16+nt*8+tig*2;
      float bv0=__ldg(b2V+c0),bv1=__ldg(b2V+c0+1),w30=__ldg(W3V+c0),w31=__ldg(W3V+c0+1);
      *(__half2*)(smc+BR2+hswz(gid,c0))  =__floats2half2_rn(w30*sg_f(DV[nt][0]+bv0),w31*sg_f(DV[nt][1]+bv1));
      *(__half2*)(smc+BR2+hswz(gid+8,c0))=__floats2half2_rn(w30*sg_f(DV[nt][2]+bv0),w31*sg_f(DV[nt][3]+bv1));
    }
    float D2[7][2][4]={};
#pragma unroll 2
    for(int ktp=0;ktp<8;ktp++){
      uint2 bf[2];
#pragma unroll
      for(int nt=0;nt<2;nt++) bf[nt]=__ldg(&g_W2L[((w*16+nt*8+gid)*8+ktp)*4+tig]);
      unsigned koff=(((unsigned)(2*ktp+chunk)^r7)<<4);
#pragma unroll
      for(int m=0;m<7;m++){
        unsigned a0,a1,a2,a3; ldsm4(a0,a1,a2,a3, rbH + m*4096 + koff);
#pragma unroll
        for(int nt=0;nt<2;nt++) mma16(D2[m][nt],a0,a1,a2,a3,bf[nt].x,bf[nt].y);
      }
    }
    __syncthreads();   // all warps done reading H
    float sgr[2][4];
#pragma unroll
    for(int nt=0;nt<2;nt++){
      int c0=w*16+nt*8+tig*2;
      float b0=__ldg(b2L+c0), b1=__ldg(b2L+c0+1);
      float z0=D2[0][nt][0]+b0, z1=D2[0][nt][1]+b1, z2=D2[0][nt][2]+b0, z3=D2[0][nt][3]+b1;
      sgr[nt][0]=sg_f(z0); sgr[nt][1]=sg_f(z1); sgr[nt][2]=sg_f(z2); sgr[nt][3]=sg_f(z3);
      *(__half2*)(smc+BH+hswz(gid,c0))  =__floats2half2_rn(sp_f(z0),sp_f(z1));
      *(__half2*)(smc+BH+hswz(gid+8,c0))=__floats2half2_rn(sp_f(z2),sp_f(z3));
    }
#pragma unroll
    for(int m=1;m<7;m++)
#pragma unroll
      for(int nt=0;nt<2;nt++){
        int c0=w*16+nt*8+tig*2;
        *(__half2*)(smc+BH+hswz(m*16+gid,c0))  =__floats2half2_rn(sgr[nt][0]*D2[m][nt][0],sgr[nt][1]*D2[m][nt][1]);
        *(__half2*)(smc+BH+hswz(m*16+8+gid,c0))=__floats2half2_rn(sgr[nt][2]*D2[m][nt][2],sgr[nt][3]*D2[m][nt][3]);
      }
  }
  __syncthreads();

  // ---------- P3: L layer3 (w0-2) | V backward + K-split grad (w4-7) ----------
  if (w<3){
    float D3[7][4]={};
#pragma unroll 2
    for(int ktp=0;ktp<8;ktp++){
      uint2 bf=__ldg(&g_W3L[((w*8+gid)*8+ktp)*4+tig]);
      unsigned koff=(((unsigned)(2*ktp+chunk)^r7)<<4);
#pragma unroll
      for(int m=0;m<7;m++){
        unsigned a0,a1,a2,a3; ldsm4(a0,a1,a2,a3, rbH + m*4096 + koff);
        mma16(D3[m],a0,a1,a2,a3,bf.x,bf.y);
      }
    }
    int c0=w*8+tig*2;
    float bb0=(c0<21)?__ldg(b3L+c0):0.f, bb1=(c0+1<21)?__ldg(b3L+c0+1):0.f;
    float z0=D3[0][0]+bb0, z1=D3[0][1]+bb1, z2=D3[0][2]+bb0, z3=D3[0][3]+bb1;
    float sg0=sg_f(z0),sg1=sg_f(z1),sg2=sg_f(z2),sg3=sg_f(z3);
    smf[WSL+gid*176+c0]=sp_f(z0);      smf[WSL+gid*176+c0+1]=sp_f(z1);
    smf[WSL+(gid+8)*176+c0]=sp_f(z2);  smf[WSL+(gid+8)*176+c0+1]=sp_f(z3);
#pragma unroll
    for(int m=1;m<7;m++){
      smf[WSL+gid*176+m*25+c0]=sg0*D3[m][0];      smf[WSL+gid*176+m*25+c0+1]=sg1*D3[m][1];
      smf[WSL+(gid+8)*176+m*25+c0]=sg2*D3[m][2];  smf[WSL+(gid+8)*176+m*25+c0+1]=sg3*D3[m][3];
    }
  } else if (w>=4){
    const int wv=w-4;
    float DB[4][4]={};
#pragma unroll 2
    for(int ktp=0;ktp<8;ktp++){
      unsigned a0,a1,a2,a3; ldsm4(a0,a1,a2,a3, rbR2 + (((2*ktp+chunk)^r7)<<4));
#pragma unroll
      for(int nt=0;nt<4;nt++){
        int n=wv*32+nt*8+gid;
        uint2 bf=__ldg(&g_W2VT[(n*8+ktp)*4+tig]);
        mma16(DB[nt],a0,a1,a2,a3,bf.x,bf.y);
      }
    }
#pragma unroll
    for(int nt=0;nt<4;nt++){
      int c0=wv*32+nt*8+tig*2;
      float2 hA=__half22float2(*(__half2*)(smc+BH1V+hswz(gid,c0)));
      float2 hB=__half22float2(*(__half2*)(smc+BH1V+hswz(gid+8,c0)));
      float r0=DB[nt][0]*(1.f-__expf(-hA.x)), r1=DB[nt][1]*(1.f-__expf(-hA.y));
      float r2=DB[nt][2]*(1.f-__expf(-hB.x)), r3=DB[nt][3]*(1.f-__expf(-hB.y));
      *(__half2*)(smc+BH1V+hswz(gid,c0))  =__floats2half2_rn(r0,r1);
      *(__half2*)(smc+BH1V+hswz(gid+8,c0))=__floats2half2_rn(r2,r3);
    }
    __syncwarp();
    // K-split grad partial: this warp's 32 K-columns (ktp = 2wv, 2wv+1)
    float DG[2][4]={};
#pragma unroll
    for(int t=0;t<2;t++){
      int ktp=2*wv+t;
      unsigned a0,a1,a2,a3; ldsm4(a0,a1,a2,a3, rbH1V + (((2*ktp+chunk)^r7)<<4));
#pragma unroll
      for(int nt=0;nt<2;nt++){
        uint2 bf=__ldg(&g_W1VT[((nt*8+gid)*8+ktp)*4+tig]);
        mma16(DG[nt],a0,a1,a2,a3,bf.x,bf.y);
      }
    }
#pragma unroll
    for(int nt=0;nt<2;nt++){
      int c=nt*8+tig*2;
      if (c<12){ smf[WSG+wv*192+gid*12+c]=DG[nt][0]; smf[WSG+wv*192+(gid+8)*12+c]=DG[nt][2]; }
      if (c+1<12){ smf[WSG+wv*192+gid*12+c+1]=DG[nt][1]; smf[WSG+wv*192+(gid+8)*12+c+1]=DG[nt][3]; }
    }
  }
  __syncthreads();

  // ---------- P5: assembly + Cholesky solve (warps 0-3, 8 lanes/element) ----------
  if (w<4){
    int gl=lane&7, grp=lane>>3, eloc=w*4+grp;
    int e=eb+eloc; bool valid=(e<B); if(!valid) e=B-1;
    const float* SLe=smf+WSL+eloc*176;
    float* SDel=smf+eloc*24;          // reuse A0 region
    float qd6[6];
#pragma unroll
    for(int j=0;j<6;j++) qd6[j]=g_qds[S][e*6+j];
    if (gl<7){
#pragma unroll
      for(int t=0;t<3;t++){
        int m=gl*3+t;
        if (m<21){
          float s=0.f;
#pragma unroll
          for(int p=0;p<6;p++) s+=qd6[p]*SLe[(1+p)*25+m];
          SDel[m]=s;
        }
      }
    }
    __syncwarp();
    int li=(gl<6)?gl:5;
    float w6[6],u6[6],Dq[6];
#pragma unroll
    for(int k=0;k<6;k++){
      float sw=0.f,su=0.f,sd=0.f;
#pragma unroll
      for(int i2=0;i2<6;i2++) if (i2>=k){
        int m=TRI(i2,k); float a=qd6[i2];
        sw+=SLe[m]*a; su+=SLe[(1+li)*25+m]*a; sd+=SDel[m]*a;
      }
      w6[k]=sw; u6[k]=su; Dq[k]=sd;
    }
    float term2=0.f;
#pragma unroll
    for(int k=0;k<6;k++) term2+=w6[k]*u6[k];
    int base=li*(li+1)/2;
    float Dw=0.f,LDq=0.f;
#pragma unroll
    for(int j2=0;j2<6;j2++) if (j2<=li){ Dw+=SDel[base+j2]*w6[j2]; LDq+=SLe[base+j2]*Dq[j2]; }
    float ci=Dw+LDq-term2;
    float qsi=g_qs[S][e*6+li];
    float gx=0.f,gy=0.f;
#pragma unroll
    for(int p=0;p<4;p++){ gx+=smf[WSG+p*192+eloc*12+2*li]; gy+=smf[WSG+p*192+eloc*12+2*li+1]; }
    float gi=-gx*sinf(qsi)+gy*cosf(qsi);
    float lo=c_LOWER[li]+0.1f, up=c_UPPER[li]-0.1f;
    float fi;
    if ((vm>>li)&1) fi=(qsi<=lo)?c_EFFORT[li]:((qsi>=up)?-c_EFFORT[li]:0.f);
    else            fi=-5.f*(1.f/(qsi-lo)-1.f/(up-qsi));
    float tau=__ldg(action+e*6+li)*c_EFFORT[li];
    float rhs=tau-ci-gi-fi;
    int gb=lane&~7;
    float accf=rhs, yvv=0.f;
#pragma unroll
    for(int j2=0;j2<6;j2++){
      float yj=__shfl_sync(FULLMASK,accf,gb+j2)/SLe[TRI(j2,j2)];
      if (gl==j2) yvv=yj;
      if (gl>j2 && gl<6) accf-=SLe[base+j2]*yj;
    }
    float acc2=yvv, xi=0.f;
#pragma unroll
    for(int j2=5;j2>=0;j2--){
      float xj=__shfl_sync(FULLMASK,acc2,gb+j2)/SLe[TRI(j2,j2)];
      if (gl==j2) xi=xj;
      if (gl<j2) acc2-=SLe[TRI(j2,gl)]*xj;
    }

    // ---- fused prep (stages 0-2) / fused final (stage 3) ----
    if (S<3){
      if (gl<6 && valid) g_kqd[S][e*6+gl]=xi;
      unsigned bits=0;
      if (gl<6 && valid){
        float q0=obs[e*12+gl], qd0=obs[e*12+6+gl];
        float qs,qds;
        if (S==0){ qs=q0+0.5f*DT*qd0;                 qds=qd0+0.5f*DT*xi; }
        else if (S==1){ qs=q0+0.5f*DT*g_qds[1][e*6+gl]; qds=qd0+0.5f*DT*xi; }
        else          { qs=q0+DT*g_qds[2][e*6+gl];      qds=qd0+DT*xi; }
        g_qs[S+1][e*6+gl]=qs; g_qds[S+1][e*6+gl]=qds;
        float lo2=c_LOWER[gl]+0.1f, up2=c_UPPER[gl]-0.1f;
        if (qs<=lo2 || qs>=up2) bits=1u<<gl;
      }
      unsigned r=__reduce_or_sync(FULLMASK,bits);
      if (lane==0 && r) atomicOr(&g_viol[S+1],(int)r);
    } else {
      if (gl<6 && valid){
        int idx=e*6+gl;
        float q0=obs[e*12+gl], qd0=obs[e*12+6+gl];
        float k0=g_kqd[0][idx],k1=g_kqd[1][idx],k2=g_kqd[2][idx];
        const float c1=DT/6.f;
        float qn=q0+c1*(g_qds[0][idx]+2.f*g_qds[1][idx]+2.f*g_qds[2][idx]+g_qds[3][idx]);
        qn=fminf(fmaxf(qn,c_LOWER[gl]),c_UPPER[gl]);
        float qdn=qd0+c1*(k0+2.f*k1+2.f*k2+xi);
        out[e*12+gl]=qn;
        out[e*12+6+gl]=qdn;
      }
    }
  }
}

extern "C" void kernel_launch(void* const* d_in, const int* in_sizes, int n_in,
                              void* d_out, int out_size)
{
  const float* obs   =(const float*)d_in[0];
  const float* action=(const float*)d_in[1];
  const float* W1L=(const float*)d_in[2];  const float* b1L=(const float*)d_in[3];
  const float* W2L=(const float*)d_in[4];  const float* b2L=(const float*)d_in[5];
  const float* W3L=(const float*)d_in[6];  const float* b3L=(const float*)d_in[7];
  const float* W1V=(const float*)d_in[8];  const float* b1V=(const float*)d_in[9];
  const float* W2V=(const float*)d_in[10]; const float* b2V=(const float*)d_in[11];
  const float* W3V=(const float*)d_in[12]; const float* b3V=(const float*)d_in[13];
  (void)b3V;
  float* out=(float*)d_out;
  int B=in_sizes[0]/12;
  if (B>MAXB) B=MAXB;

  cudaFuncSetAttribute(accel_mma_kernel, cudaFuncAttributeMaxDynamicSharedMemorySize, SMEM_BYTES);

  int nbA=(B+15)/16;
  int nbI=(B*6+255)/256; if (nbI<57) nbI=57;

  zero_viol_kernel<<<1,32>>>();
  init_kernel<<<nbI,256>>>(obs,W1L,b1L,W2L,W3L,W1V,b1V,W2V,B);
  for (int s=0;s<4;s++){
    accel_mma_kernel<<<nbA,256,SMEM_BYTES>>>(s,obs,action,out,b2L,b3L,b2V,W3V,B);
  }
}